// round 6
// baseline (speedup 1.0000x reference)
#include <cuda_runtime.h>
#include <cuda_bf16.h>
#include <cuda_fp16.h>
#include <math.h>
#include <stdint.h>

#define T_STEPS 24
#define NN 50000
#define NPAD 50048
#define EE 1600000
#define F 16
#define H 64
#define LH 128
#define SCAN_NB 98

#define NTILES64 782            // NPAD/64
#define NCTAS 148
#define NGRP 37                 // CTA groups per nb

// persistent-kernel smem layout
#define W2_OFF 2048             // 64*64 floats = 16384
#define B2_OFF 18432            // 64 floats
#define BOFF 18688              // B hi+lo: 2 * 128 * 400 = 102400
#define AOFF (BOFF + 102400)    // A double buffer: 2 * 51200
#define PERSIST_SMEM (AOFF + 2 * 51200)   // 223488

// ---------------- helpers ----------------
__device__ __forceinline__ uint32_t smem_u32(const void* p) {
    uint32_t a;
    asm("{ .reg .u64 t; cvta.to.shared.u64 t, %1; cvt.u32.u64 %0, t; }" : "=r"(a) : "l"(p));
    return a;
}
__device__ __forceinline__ void ldsm4(uint32_t* r, uint32_t addr) {
    asm volatile("ldmatrix.sync.aligned.m8n8.x4.shared.b16 {%0,%1,%2,%3}, [%4];"
                 : "=r"(r[0]), "=r"(r[1]), "=r"(r[2]), "=r"(r[3]) : "r"(addr));
}
__device__ __forceinline__ void mma16816(float* c, const uint32_t* a, const uint32_t* b) {
    asm volatile(
        "mma.sync.aligned.m16n8k16.row.col.f32.bf16.bf16.f32 "
        "{%0,%1,%2,%3}, {%4,%5,%6,%7}, {%8,%9}, {%0,%1,%2,%3};"
        : "+f"(c[0]), "+f"(c[1]), "+f"(c[2]), "+f"(c[3])
        : "r"(a[0]), "r"(a[1]), "r"(a[2]), "r"(a[3]), "r"(b[0]), "r"(b[1]));
}
__device__ __forceinline__ void cp16(uint32_t dst, const void* src) {
    asm volatile("cp.async.cg.shared.global [%0], [%1], 16;" :: "r"(dst), "l"(src));
}
__device__ __forceinline__ float sigf(float x) {
    return __fdividef(1.0f, 1.0f + __expf(-x));
}
__device__ __forceinline__ float tanhfast(float x) {
    float e = __expf(-2.0f * fabsf(x));
    float r = __fdividef(1.0f - e, 1.0f + e);
    return copysignf(r, x);
}
#define BAR_LSTM() asm volatile("bar.sync 1, 256;" ::: "memory")

// ---------------- scratch ----------------
__device__ int   d_deg[NN];
__device__ int   d_rowptr[NN + 1];
__device__ int   d_cursor[NN];
__device__ int   d_csr[EE];
__device__ int   d_blocksum[128];
__device__ float d_dinv[NN];
__device__ unsigned d_bar;
__device__ __half d_xh[19200000];                 // [n][t*16+c]  (x * dinv[n])
__device__ __half d_h1[76800000];                 // [t][n][64]   (h1 * dinv[n])
__device__ __nv_bfloat16 d_h2h[76873728];         // [t][NPAD][64] hi
__device__ __nv_bfloat16 d_h2l[76873728];         // lo
__device__ __nv_bfloat16 d_hh0[6406144];          // [NPAD][128]
__device__ __nv_bfloat16 d_hl0[6406144];
__device__ __nv_bfloat16 d_hh1[6406144];
__device__ __nv_bfloat16 d_hl1[6406144];
__device__ float d_cs2[6406144];                  // [nb][NPAD][32]
__device__ uint4 d_Bp[2 * 512 * 24];              // bf16 hi/lo weights, reordered cols

// ---------------- CSR build ----------------
__global__ void deg_kernel(const int* __restrict__ ei) {
    int e = blockIdx.x * 256 + threadIdx.x;
    if (e < EE) atomicAdd(&d_deg[ei[EE + e]], 1);
}
__global__ void dinv_scan_kernel() {
    __shared__ int s[512];
    int tid = threadIdx.x;
    int i = blockIdx.x * 512 + tid;
    if (i == 0) d_bar = 0;
    int v = (i < NN) ? d_deg[i] : 0;
    if (i < NN) d_dinv[i] = rsqrtf((float)v + 1.0f);
    s[tid] = v;
    __syncthreads();
    #pragma unroll
    for (int off = 1; off < 512; off <<= 1) {
        int t = (tid >= off) ? s[tid - off] : 0;
        __syncthreads();
        s[tid] += t;
        __syncthreads();
    }
    if (i < NN) d_rowptr[i + 1] = s[tid];
    if (tid == 511) d_blocksum[blockIdx.x] = s[511];
}
__global__ void scan_add2_kernel() {
    __shared__ int soff;
    int sbk = blockIdx.x >> 1;
    if (threadIdx.x == 0) {
        int o = 0;
        for (int j = 0; j < sbk; j++) o += d_blocksum[j];
        soff = o;
    }
    __syncthreads();
    int i = blockIdx.x * 256 + threadIdx.x;
    if (i == 0) { d_rowptr[0] = 0; d_cursor[0] = 0; }
    if (i < NN) {
        int v = d_rowptr[i + 1] + soff;
        d_rowptr[i + 1] = v;
        if (i + 1 < NN) d_cursor[i + 1] = v;
    }
}

// ---------------- fused fill: csr_fill + xprep + bprep ----------------
__global__ void fused_fill_kernel(const int* __restrict__ ei,
                                  const float* __restrict__ x_seq,
                                  const float* __restrict__ Wih,
                                  const float* __restrict__ Whh) {
    int b = blockIdx.x;
    if (b < 6250) {
        int e = b * 256 + threadIdx.x;
        int s = ei[e];
        int d = ei[EE + e];
        int idx = atomicAdd(&d_cursor[d], 1);
        d_csr[idx] = s;
    } else if (b < 25000) {
        int id = (b - 6250) * 256 + threadIdx.x;
        if (id >= NN * 96) return;
        int n = id / 96, r = id % 96;
        int t = r >> 2, c4 = r & 3;
        float dn = d_dinv[n];
        float4 v = *(const float4*)(x_seq + ((size_t)t * NN + n) * F + c4 * 4);
        __half h[4] = {__float2half_rn(v.x * dn), __float2half_rn(v.y * dn),
                       __float2half_rn(v.z * dn), __float2half_rn(v.w * dn)};
        *(uint2*)(d_xh + (size_t)n * 384 + r * 4) = *(uint2*)h;
    } else {
        int id = (b - 25000) * 256 + threadIdx.x;
        if (id >= 2 * 512 * 24) return;
        int p = id / (512 * 24);
        int rem = id - p * (512 * 24);
        int cg = rem / 24, u = rem % 24;
        int nb = cg >> 7, c = cg & 127;
        int wn = c >> 5, g = (c >> 3) & 3, s = c & 7;
        int jg = nb * 32 + wn * 8 + s;
        int G = g * 128 + jg;
        union { __nv_bfloat16 h[8]; uint4 q; } up;
        #pragma unroll
        for (int e = 0; e < 8; e++) {
            int k = u * 8 + e;
            float v = (k < 64) ? Wih[G * 64 + k] : Whh[G * 128 + (k - 64)];
            __nv_bfloat16 hi = __float2bfloat16_rn(v);
            up.h[e] = p ? __float2bfloat16_rn(v - __bfloat162float(hi)) : hi;
        }
        d_Bp[(size_t)(p * 512 + cg) * 24 + u] = up.q;
    }
}

// ---------------- fused agg1 + mm1 (8-t chunks, dinv folded) ----------------
__global__ void __launch_bounds__(256) agg1mm1_kernel(const float* __restrict__ W1,
                                                      const float* __restrict__ b1) {
    __shared__ float W1s[F * H];
    __shared__ float b1s[H];
    __shared__ float ys[8][128];
    int tid = threadIdx.x, w = tid >> 5, lane = tid & 31;
    for (int i = tid; i < F * H; i += 256) W1s[i] = W1[i];
    if (tid < H) b1s[tid] = b1[tid];
    int n = blockIdx.x * 8 + w;
    int q = blockIdx.y;
    float dn = d_dinv[n];
    const uint2* xr = (const uint2*)d_xh;
    uint2 u = xr[(size_t)n * 96 + q * 32 + lane];
    float2 p0 = __half22float2(*(__half2*)&u.x);
    float2 p1 = __half22float2(*(__half2*)&u.y);
    float a0 = p0.x, a1 = p0.y, a2 = p1.x, a3 = p1.y;
    int e = d_rowptr[n], e1 = d_rowptr[n + 1];
    for (; e + 8 <= e1; e += 8) {
        int si[8];
        #pragma unroll
        for (int k = 0; k < 8; k++) si[k] = d_csr[e + k];
        #pragma unroll
        for (int k = 0; k < 8; k++) {
            uint2 v = xr[(size_t)si[k] * 96 + q * 32 + lane];
            float2 q0 = __half22float2(*(__half2*)&v.x);
            float2 q1 = __half22float2(*(__half2*)&v.y);
            a0 += q0.x; a1 += q0.y; a2 += q1.x; a3 += q1.y;
        }
    }
    for (; e < e1; e++) {
        int s = d_csr[e];
        uint2 v = xr[(size_t)s * 96 + q * 32 + lane];
        float2 q0 = __half22float2(*(__half2*)&v.x);
        float2 q1 = __half22float2(*(__half2*)&v.y);
        a0 += q0.x; a1 += q0.y; a2 += q1.x; a3 += q1.y;
    }
    ys[w][lane * 4 + 0] = a0 * dn; ys[w][lane * 4 + 1] = a1 * dn;
    ys[w][lane * 4 + 2] = a2 * dn; ys[w][lane * 4 + 3] = a3 * dn;
    __syncthreads();
    int n2 = tid >> 5, t2 = lane >> 2, jq = lane & 3;
    int ng = blockIdx.x * 8 + n2;
    float dscale = d_dinv[ng];
    float yv[16];
    #pragma unroll
    for (int k = 0; k < 16; k++) yv[k] = ys[n2][t2 * 16 + k];
    float o[16];
    #pragma unroll
    for (int jj = 0; jj < 16; jj++) o[jj] = b1s[jq * 16 + jj];
    #pragma unroll
    for (int k = 0; k < 16; k++)
        #pragma unroll
        for (int jj = 0; jj < 16; jj++)
            o[jj] = fmaf(yv[k], W1s[k * 64 + jq * 16 + jj], o[jj]);
    __half hp[16];
    #pragma unroll
    for (int jj = 0; jj < 16; jj++)
        hp[jj] = __float2half_rn(fmaxf(o[jj], 0.0f) * dscale);
    int tg = q * 8 + t2;
    __half* dst = d_h1 + ((size_t)tg * NN + ng) * 64 + jq * 16;
    *(uint4*)dst = *(uint4*)hp;
    *(uint4*)(dst + 8) = *(uint4*)(hp + 8);
}

// ---------------- GCN node (agg2+mm2 for one node, one warp) ----------------
__device__ __forceinline__ void gcn_node(int n, int tp, int lane,
                                         const float* W2s, const float* b2s) {
    float dn = d_dinv[n];
    const uint* h1u = (const uint*)d_h1 + (size_t)tp * NN * 32;
    uint su = h1u[(size_t)n * 32 + lane];
    float2 sp = __half22float2(*(__half2*)&su);
    float a0 = sp.x, a1 = sp.y;
    int e = d_rowptr[n], e1 = d_rowptr[n + 1];
    for (; e + 8 <= e1; e += 8) {
        int si[8];
        #pragma unroll
        for (int u2 = 0; u2 < 8; u2++) si[u2] = d_csr[e + u2];
        #pragma unroll
        for (int u2 = 0; u2 < 8; u2++) {
            uint v = h1u[(size_t)si[u2] * 32 + lane];
            float2 p = __half22float2(*(__half2*)&v);
            a0 += p.x; a1 += p.y;
        }
    }
    for (; e < e1; e++) {
        int s2 = d_csr[e];
        uint v = h1u[(size_t)s2 * 32 + lane];
        float2 p = __half22float2(*(__half2*)&v);
        a0 += p.x; a1 += p.y;
    }
    a0 *= dn; a1 *= dn;
    float o0 = b2s[2 * lane], o1 = b2s[2 * lane + 1];
    #pragma unroll
    for (int k = 0; k < 64; k++) {
        float zk = __shfl_sync(0xffffffffu, (k & 1) ? a1 : a0, k >> 1);
        o0 = fmaf(zk, W2s[k * 64 + 2 * lane], o0);
        o1 = fmaf(zk, W2s[k * 64 + 2 * lane + 1], o1);
    }
    o0 = fmaxf(o0, 0.0f); o1 = fmaxf(o1, 0.0f);
    __nv_bfloat16 h0 = __float2bfloat16_rn(o0);
    __nv_bfloat16 h1b = __float2bfloat16_rn(o1);
    __nv_bfloat16 l0 = __float2bfloat16_rn(o0 - __bfloat162float(h0));
    __nv_bfloat16 l1 = __float2bfloat16_rn(o1 - __bfloat162float(h1b));
    size_t base = ((size_t)tp * NPAD + n) * 64 + 2 * lane;
    *(uint*)(d_h2h + base) =
        (uint)__bfloat16_as_ushort(h0) | ((uint)__bfloat16_as_ushort(h1b) << 16);
    *(uint*)(d_h2l + base) =
        (uint)__bfloat16_as_ushort(l0) | ((uint)__bfloat16_as_ushort(l1) << 16);
}

// ---------------- A staging (LSTM warps only, cp.async) ----------------
__device__ __forceinline__ void stageA(
    char* smem, uint32_t sb, int buf, int tile, bool zero_h,
    const __nv_bfloat16* h2h, const __nv_bfloat16* h2l,
    const __nv_bfloat16* hhp, const __nv_bfloat16* hlp, int tid) {
    int row0 = tile * 64;
    uint32_t bufb = sb + AOFF + buf * 51200;
    #pragma unroll
    for (int it = 0; it < 12; it++) {
        int i = tid + it * 256;                  // 0..3071
        int p = i / 1536;
        int rem = i - p * 1536;
        int row = rem / 24, u = rem % 24;
        uint32_t dst = bufb + p * 25600 + row * 400 + u * 16;
        if (u < 8) {
            cp16(dst, (p ? h2l : h2h) + (size_t)(row0 + row) * 64 + u * 8);
        } else if (!zero_h) {
            cp16(dst, (p ? hlp : hhp) + (size_t)(row0 + row) * 128 + (u - 8) * 8);
        } else {
            *(uint4*)(smem + AOFF + buf * 51200 + p * 25600 + row * 400 + u * 16) =
                make_uint4(0, 0, 0, 0);
        }
    }
    asm volatile("cp.async.commit_group;" ::: "memory");
}

// ---------------- grid barrier ----------------
__device__ __forceinline__ void gridbar(int tid, int phase) {
    __threadfence();
    __syncthreads();
    if (tid == 0) {
        atomicAdd(&d_bar, 1u);
        unsigned target = (unsigned)(NCTAS * phase);
        unsigned v;
        do {
            asm volatile("ld.acquire.gpu.global.u32 %0, [%1];"
                         : "=r"(v) : "l"(&d_bar) : "memory");
            if (v < target) asm volatile("nanosleep.u32 32;");
        } while (v < target);
    }
    __syncthreads();
}

// ---------------- persistent LSTM + warp-specialized GCN layer 2 ----------------
__global__ void __launch_bounds__(384, 1) lstm_persist(const float* __restrict__ bih,
                                                       const float* __restrict__ bhh,
                                                       const float* __restrict__ W2,
                                                       const float* __restrict__ b2) {
    extern __shared__ char smem[];
    float* bs = (float*)smem;
    float* W2s = (float*)(smem + W2_OFF);
    float* b2s = (float*)(smem + B2_OFF);
    uint32_t sb = smem_u32(smem);
    const int tid = threadIdx.x, lane = tid & 31, wid = tid >> 5;
    const int nb = blockIdx.x & 3;
    const int gidx = blockIdx.x >> 2;
    const int cnt = (gidx < NTILES64 - NGRP * 21) ? 22 : 21;

    // one-time smem init (all 384 threads)
    for (int j = tid; j < 512; j += 384) bs[j] = bih[j] + bhh[j];
    for (int i = tid; i < H * H; i += 384) W2s[i] = W2[i];
    if (tid < H) b2s[tid] = b2[tid];
    for (int i = tid; i < 2 * 128 * 24; i += 384) {
        int p = i / (128 * 24);
        int rem = i - p * (128 * 24);
        int col = rem / 24, u = rem % 24;
        uint4 v = d_Bp[(size_t)(p * 512 + nb * 128 + col) * 24 + u];
        *(uint4*)(smem + BOFF + p * 51200 + col * 400 + u * 16) = v;
    }
    __syncthreads();

    // prologue: h2 for t'=0,1 with all 12 warps
    {
        int gw = blockIdx.x * 12 + wid;
        for (int tp = 0; tp < 2; tp++)
            for (int n = gw; n < NN; n += NCTAS * 12)
                gcn_node(n, tp, lane, W2s, b2s);
    }
    gridbar(tid, 1);

    const int wm = wid & 1;
    const int wn = wid >> 1;
    const int q = lane >> 3, r8 = lane & 7;
    const uint32_t aRowOff = (uint32_t)((wm * 32 + (q & 1) * 8 + r8) * 400 + ((q >> 1) * 8) * 2);
    const uint32_t bRowBase = (uint32_t)((wn * 32 + (q >> 1) * 8 + r8) * 400 + (q & 1) * 16);
    const int gq = lane >> 2, tq = lane & 3;

    for (int t = 0; t < T_STEPS; t++) {
        if (wid < 8) {
            const __nv_bfloat16* h2h = d_h2h + (size_t)t * NPAD * 64;
            const __nv_bfloat16* h2l = d_h2l + (size_t)t * NPAD * 64;
            const __nv_bfloat16* hhp = (t & 1) ? d_hh1 : d_hh0;
            const __nv_bfloat16* hlp = (t & 1) ? d_hl1 : d_hl0;
            __nv_bfloat16* hhn = (t & 1) ? d_hh0 : d_hh1;
            __nv_bfloat16* hln = (t & 1) ? d_hl0 : d_hl1;
            const bool z = (t == 0);

            stageA(smem, sb, 0, gidx, z, h2h, h2l, hhp, hlp, tid);

            for (int k = 0; k < cnt; k++) {
                int tile = gidx + k * NGRP;
                if (k + 1 < cnt) {
                    stageA(smem, sb, (k + 1) & 1, gidx + (k + 1) * NGRP, z, h2h, h2l, hhp, hlp, tid);
                    asm volatile("cp.async.wait_group 1;" ::: "memory");
                } else {
                    asm volatile("cp.async.wait_group 0;" ::: "memory");
                }
                BAR_LSTM();

                float acc[2][4][4];
                #pragma unroll
                for (int mi = 0; mi < 2; mi++)
                    #pragma unroll
                    for (int nt = 0; nt < 4; nt++)
                        #pragma unroll
                        for (int r = 0; r < 4; r++) acc[mi][nt][r] = 0.0f;

                uint32_t abufb = sb + AOFF + (k & 1) * 51200;
                #pragma unroll 1
                for (int pass = 0; pass < 3; pass++) {
                    uint32_t aB = abufb + (pass == 2 ? 25600 : 0) + aRowOff;
                    uint32_t bB = sb + BOFF + (pass == 1 ? 51200 : 0) + bRowBase;
                    #pragma unroll 1
                    for (int ks = 0; ks < 12; ks++) {
                        uint32_t a[2][4];
                        ldsm4(a[0], aB + ks * 32);
                        ldsm4(a[1], aB + 16 * 400 + ks * 32);
                        uint32_t b[4][2];
                        {
                            uint32_t t4[4];
                            ldsm4(t4, bB + ks * 32);
                            b[0][0] = t4[0]; b[0][1] = t4[1];
                            b[1][0] = t4[2]; b[1][1] = t4[3];
                        }
                        {
                            uint32_t t4[4];
                            ldsm4(t4, bB + 16 * 400 + ks * 32);
                            b[2][0] = t4[0]; b[2][1] = t4[1];
                            b[3][0] = t4[2]; b[3][1] = t4[3];
                        }
                        #pragma unroll
                        for (int mi = 0; mi < 2; mi++)
                            #pragma unroll
                            for (int nt = 0; nt < 4; nt++)
                                mma16816(acc[mi][nt], a[mi], b[nt]);
                    }
                }

                int row0 = tile * 64;
                #pragma unroll
                for (int mi = 0; mi < 2; mi++) {
                    #pragma unroll
                    for (int h = 0; h < 2; h++) {
                        int rl = wm * 32 + mi * 16 + h * 8 + gq;
                        int n = row0 + rl;
                        float* cptr = d_cs2 + ((size_t)nb * NPAD + n) * 32 + wn * 8 + tq * 2;
                        float2 cp = z ? make_float2(0.0f, 0.0f) : *(float2*)cptr;
                        uint hiPack = 0, loPack = 0;
                        #pragma unroll
                        for (int p = 0; p < 2; p++) {
                            int jgl = nb * 32 + wn * 8 + tq * 2 + p;
                            int ci = h * 2 + p;
                            float gi = acc[mi][0][ci] + bs[jgl];
                            float gf = acc[mi][1][ci] + bs[128 + jgl];
                            float gG = acc[mi][2][ci] + bs[256 + jgl];
                            float go = acc[mi][3][ci] + bs[384 + jgl];
                            float cold = p ? cp.y : cp.x;
                            float cn = sigf(gf) * cold + sigf(gi) * tanhfast(gG);
                            float hv = sigf(go) * tanhfast(cn);
                            if (p) cp.y = cn; else cp.x = cn;
                            __nv_bfloat16 hi = __float2bfloat16_rn(hv);
                            __nv_bfloat16 lo = __float2bfloat16_rn(hv - __bfloat162float(hi));
                            hiPack |= ((uint)__bfloat16_as_ushort(hi)) << (16 * p);
                            loPack |= ((uint)__bfloat16_as_ushort(lo)) << (16 * p);
                        }
                        *(float2*)cptr = cp;
                        size_t hb = (size_t)n * 128 + nb * 32 + wn * 8 + tq * 2;
                        *(uint*)(hhn + hb) = hiPack;
                        *(uint*)(hln + hb) = loPack;
                    }
                }
                BAR_LSTM();
            }
        } else {
            // GCN warps: produce h2 for step t+2
            int tp = t + 2;
            if (tp < T_STEPS) {
                int gw = blockIdx.x * 4 + (wid - 8);
                for (int n = gw; n < NN; n += NCTAS * 4)
                    gcn_node(n, tp, lane, W2s, b2s);
            }
        }
        if (t < T_STEPS - 1) gridbar(tid, t + 2);
    }
}

// ---------------- FC head ----------------
__global__ void fc_kernel(const __nv_bfloat16* __restrict__ hh,
                          const __nv_bfloat16* __restrict__ hl,
                          const float* __restrict__ Wf1, const float* __restrict__ bf1,
                          const float* __restrict__ Wf2, const float* __restrict__ bf2,
                          float* __restrict__ out) {
    __shared__ float Ws[LH * 32];
    __shared__ float hsm[32][LH];
    int tid = threadIdx.x;
    for (int i = tid; i < LH * 32; i += 256) Ws[i] = Wf1[i];
    int n0 = blockIdx.x * 32;
    for (int i = tid; i < 32 * LH; i += 256) {
        int nl = i >> 7, k = i & 127;
        int n = n0 + nl;
        float v = 0.0f;
        if (n < NN) {
            size_t idx = (size_t)n * 128 + k;
            v = __bfloat162float(hh[idx]) + __bfloat162float(hl[idx]);
        }
        hsm[nl][k] = v;
    }
    __syncthreads();
    int w = tid >> 5, lane = tid & 31;
    float wf2 = Wf2[lane];
    float bb1 = bf1[lane];
    for (int r = 0; r < 4; r++) {
        int nl = w * 4 + r;
        int n = n0 + nl;
        float acc = bb1;
        #pragma unroll
        for (int k = 0; k < LH; k++) acc = fmaf(hsm[nl][k], Ws[k * 32 + lane], acc);
        acc = fmaxf(acc, 0.0f) * wf2;
        #pragma unroll
        for (int off = 16; off > 0; off >>= 1)
            acc += __shfl_down_sync(0xffffffffu, acc, off);
        if (lane == 0 && n < NN) out[n] = acc + bf2[0];
    }
}

// ---------------- launcher ----------------
extern "C" void kernel_launch(void* const* d_in, const int* in_sizes, int n_in,
                              void* d_out, int out_size) {
    const float* x_seq = (const float*)d_in[0];
    const int*   ei    = (const int*)d_in[1];
    const float* W1    = (const float*)d_in[2];
    const float* b1    = (const float*)d_in[3];
    const float* W2    = (const float*)d_in[4];
    const float* b2    = (const float*)d_in[5];
    const float* Wih   = (const float*)d_in[6];
    const float* Whh   = (const float*)d_in[7];
    const float* bih   = (const float*)d_in[8];
    const float* bhh   = (const float*)d_in[9];
    const float* Wf1   = (const float*)d_in[10];
    const float* bf1   = (const float*)d_in[11];
    const float* Wf2   = (const float*)d_in[12];
    const float* bf2   = (const float*)d_in[13];
    float* out = (float*)d_out;

    cudaFuncSetAttribute(lstm_persist, cudaFuncAttributeMaxDynamicSharedMemorySize,
                         PERSIST_SMEM);

    void* degp;
    cudaGetSymbolAddress(&degp, d_deg);
    cudaMemsetAsync(degp, 0, NN * sizeof(int));

    __nv_bfloat16 *hh0, *hl0;
    cudaGetSymbolAddress((void**)&hh0, d_hh0);
    cudaGetSymbolAddress((void**)&hl0, d_hl0);

    deg_kernel<<<(EE + 255) / 256, 256>>>(ei);
    dinv_scan_kernel<<<SCAN_NB, 512>>>();
    scan_add2_kernel<<<(NN + 255) / 256, 256>>>();
    fused_fill_kernel<<<25096, 256>>>(ei, x_seq, Wih, Whh);
    agg1mm1_kernel<<<dim3(NN / 8, 3), 256>>>(W1, b1);
    lstm_persist<<<NCTAS, 384, PERSIST_SMEM>>>(bih, bhh, W2, b2);
    fc_kernel<<<(NN + 31) / 32, 256>>>(hh0, hl0, Wf1, bf1, Wf2, bf2, out);
}

// round 7
// speedup vs baseline: 1.4732x; 1.4732x over previous
#include <cuda_runtime.h>
#include <cuda_bf16.h>
#include <cuda_fp16.h>
#include <math.h>
#include <stdint.h>

#define T_STEPS 24
#define NN 50000
#define NPAD 50048
#define EE 1600000
#define F 16
#define H 64
#define LH 128
#define SCAN_NB 98

#define NTILES64 782            // NPAD/64
#define NCTAS 148
#define NGRP 37                 // CTA groups per nb

// persistent-kernel smem layout
#define BIAS_OFF 0              // 512 floats = 2048 B
#define BOFF 2048               // B hi+lo: 2 * 128 * 400 = 102400
#define AOFF (2048 + 102400)    // A double buffer: 2 * 51200
#define PERSIST_SMEM (AOFF + 2 * 51200)   // 206848

// ---------------- helpers ----------------
__device__ __forceinline__ uint32_t smem_u32(const void* p) {
    uint32_t a;
    asm("{ .reg .u64 t; cvta.to.shared.u64 t, %1; cvt.u32.u64 %0, t; }" : "=r"(a) : "l"(p));
    return a;
}
__device__ __forceinline__ void ldsm4(uint32_t* r, uint32_t addr) {
    asm volatile("ldmatrix.sync.aligned.m8n8.x4.shared.b16 {%0,%1,%2,%3}, [%4];"
                 : "=r"(r[0]), "=r"(r[1]), "=r"(r[2]), "=r"(r[3]) : "r"(addr));
}
__device__ __forceinline__ void mma16816(float* c, const uint32_t* a, const uint32_t* b) {
    asm volatile(
        "mma.sync.aligned.m16n8k16.row.col.f32.bf16.bf16.f32 "
        "{%0,%1,%2,%3}, {%4,%5,%6,%7}, {%8,%9}, {%0,%1,%2,%3};"
        : "+f"(c[0]), "+f"(c[1]), "+f"(c[2]), "+f"(c[3])
        : "r"(a[0]), "r"(a[1]), "r"(a[2]), "r"(a[3]), "r"(b[0]), "r"(b[1]));
}
__device__ __forceinline__ void cp16(uint32_t dst, const void* src) {
    asm volatile("cp.async.cg.shared.global [%0], [%1], 16;" :: "r"(dst), "l"(src));
}
__device__ __forceinline__ float sigf(float x) {
    return __fdividef(1.0f, 1.0f + __expf(-x));
}
__device__ __forceinline__ float tanhfast(float x) {
    float e = __expf(-2.0f * fabsf(x));
    float r = __fdividef(1.0f - e, 1.0f + e);
    return copysignf(r, x);
}

// ---------------- scratch ----------------
__device__ int   d_deg[NN];
__device__ int   d_rowptr[NN + 1];
__device__ int   d_cursor[NN];
__device__ int   d_csr[EE];
__device__ int   d_blocksum[128];
__device__ float d_dinv[NN];
__device__ unsigned d_bar;
__device__ __half d_xh[19200000];                 // [n][t*16+c]  (x * dinv[n])
__device__ __half d_h1[76800000];                 // [t][n][64]   (h1 * dinv[n])
__device__ __nv_bfloat16 d_h2h[76873728];         // [t][NPAD][64] hi
__device__ __nv_bfloat16 d_h2l[76873728];         // lo
__device__ __nv_bfloat16 d_hh0[6406144];          // [NPAD][128]
__device__ __nv_bfloat16 d_hl0[6406144];
__device__ __nv_bfloat16 d_hh1[6406144];
__device__ __nv_bfloat16 d_hl1[6406144];
__device__ float d_cs2[6406144];                  // [nb][NPAD][32]
__device__ uint4 d_Bp[2 * 512 * 24];              // bf16 hi/lo weights, reordered cols

// ---------------- CSR build ----------------
__global__ void deg_kernel(const int* __restrict__ ei) {
    int e = blockIdx.x * 256 + threadIdx.x;
    if (e < EE) atomicAdd(&d_deg[ei[EE + e]], 1);
}
__global__ void dinv_scan_kernel() {
    __shared__ int s[512];
    int tid = threadIdx.x;
    int i = blockIdx.x * 512 + tid;
    if (i == 0) d_bar = 0;
    int v = (i < NN) ? d_deg[i] : 0;
    if (i < NN) d_dinv[i] = rsqrtf((float)v + 1.0f);
    s[tid] = v;
    __syncthreads();
    #pragma unroll
    for (int off = 1; off < 512; off <<= 1) {
        int t = (tid >= off) ? s[tid - off] : 0;
        __syncthreads();
        s[tid] += t;
        __syncthreads();
    }
    if (i < NN) d_rowptr[i + 1] = s[tid];
    if (tid == 511) d_blocksum[blockIdx.x] = s[511];
}
__global__ void scan_add2_kernel() {
    __shared__ int soff;
    int sbk = blockIdx.x >> 1;
    if (threadIdx.x == 0) {
        int o = 0;
        for (int j = 0; j < sbk; j++) o += d_blocksum[j];
        soff = o;
    }
    __syncthreads();
    int i = blockIdx.x * 256 + threadIdx.x;
    if (i == 0) { d_rowptr[0] = 0; d_cursor[0] = 0; }
    if (i < NN) {
        int v = d_rowptr[i + 1] + soff;
        d_rowptr[i + 1] = v;
        if (i + 1 < NN) d_cursor[i + 1] = v;
    }
}

// ---------------- fused fill: csr_fill + xprep + bprep ----------------
__global__ void fused_fill_kernel(const int* __restrict__ ei,
                                  const float* __restrict__ x_seq,
                                  const float* __restrict__ Wih,
                                  const float* __restrict__ Whh) {
    int b = blockIdx.x;
    if (b < 6250) {
        int e = b * 256 + threadIdx.x;
        int s = ei[e];
        int d = ei[EE + e];
        int idx = atomicAdd(&d_cursor[d], 1);
        d_csr[idx] = s;
    } else if (b < 25000) {
        int id = (b - 6250) * 256 + threadIdx.x;
        if (id >= NN * 96) return;
        int n = id / 96, r = id % 96;
        int t = r >> 2, c4 = r & 3;
        float dn = d_dinv[n];
        float4 v = *(const float4*)(x_seq + ((size_t)t * NN + n) * F + c4 * 4);
        __half h[4] = {__float2half_rn(v.x * dn), __float2half_rn(v.y * dn),
                       __float2half_rn(v.z * dn), __float2half_rn(v.w * dn)};
        *(uint2*)(d_xh + (size_t)n * 384 + r * 4) = *(uint2*)h;
    } else {
        int id = (b - 25000) * 256 + threadIdx.x;
        if (id >= 2 * 512 * 24) return;
        int p = id / (512 * 24);
        int rem = id - p * (512 * 24);
        int cg = rem / 24, u = rem % 24;
        int nb = cg >> 7, c = cg & 127;
        int wn = c >> 5, g = (c >> 3) & 3, s = c & 7;
        int jg = nb * 32 + wn * 8 + s;
        int G = g * 128 + jg;
        union { __nv_bfloat16 h[8]; uint4 q; } up;
        #pragma unroll
        for (int e = 0; e < 8; e++) {
            int k = u * 8 + e;
            float v = (k < 64) ? Wih[G * 64 + k] : Whh[G * 128 + (k - 64)];
            __nv_bfloat16 hi = __float2bfloat16_rn(v);
            up.h[e] = p ? __float2bfloat16_rn(v - __bfloat162float(hi)) : hi;
        }
        d_Bp[(size_t)(p * 512 + cg) * 24 + u] = up.q;
    }
}

// ---------------- fused agg1 + mm1 (8-t chunks, dinv folded, MLP8) ----------------
__global__ void __launch_bounds__(256) agg1mm1_kernel(const float* __restrict__ W1,
                                                      const float* __restrict__ b1) {
    __shared__ float W1s[F * H];
    __shared__ float b1s[H];
    __shared__ float ys[8][128];
    int tid = threadIdx.x, w = tid >> 5, lane = tid & 31;
    for (int i = tid; i < F * H; i += 256) W1s[i] = W1[i];
    if (tid < H) b1s[tid] = b1[tid];
    int n = blockIdx.x * 8 + w;
    int q = blockIdx.y;
    float dn = d_dinv[n];
    const uint2* xr = (const uint2*)d_xh;
    uint2 u = xr[(size_t)n * 96 + q * 32 + lane];
    float2 p0 = __half22float2(*(__half2*)&u.x);
    float2 p1 = __half22float2(*(__half2*)&u.y);
    float a0 = p0.x, a1 = p0.y, a2 = p1.x, a3 = p1.y;
    int e = d_rowptr[n], e1 = d_rowptr[n + 1];
    for (; e + 8 <= e1; e += 8) {
        int si[8];
        #pragma unroll
        for (int k = 0; k < 8; k++) si[k] = d_csr[e + k];
        #pragma unroll
        for (int k = 0; k < 8; k++) {
            uint2 v = xr[(size_t)si[k] * 96 + q * 32 + lane];
            float2 q0 = __half22float2(*(__half2*)&v.x);
            float2 q1 = __half22float2(*(__half2*)&v.y);
            a0 += q0.x; a1 += q0.y; a2 += q1.x; a3 += q1.y;
        }
    }
    for (; e < e1; e++) {
        int s = d_csr[e];
        uint2 v = xr[(size_t)s * 96 + q * 32 + lane];
        float2 q0 = __half22float2(*(__half2*)&v.x);
        float2 q1 = __half22float2(*(__half2*)&v.y);
        a0 += q0.x; a1 += q0.y; a2 += q1.x; a3 += q1.y;
    }
    ys[w][lane * 4 + 0] = a0 * dn; ys[w][lane * 4 + 1] = a1 * dn;
    ys[w][lane * 4 + 2] = a2 * dn; ys[w][lane * 4 + 3] = a3 * dn;
    __syncthreads();
    int n2 = tid >> 5, t2 = lane >> 2, jq = lane & 3;
    int ng = blockIdx.x * 8 + n2;
    float dscale = d_dinv[ng];
    float yv[16];
    #pragma unroll
    for (int k = 0; k < 16; k++) yv[k] = ys[n2][t2 * 16 + k];
    float o[16];
    #pragma unroll
    for (int jj = 0; jj < 16; jj++) o[jj] = b1s[jq * 16 + jj];
    #pragma unroll
    for (int k = 0; k < 16; k++)
        #pragma unroll
        for (int jj = 0; jj < 16; jj++)
            o[jj] = fmaf(yv[k], W1s[k * 64 + jq * 16 + jj], o[jj]);
    __half hp[16];
    #pragma unroll
    for (int jj = 0; jj < 16; jj++)
        hp[jj] = __float2half_rn(fmaxf(o[jj], 0.0f) * dscale);
    int tg = q * 8 + t2;
    __half* dst = d_h1 + ((size_t)tg * NN + ng) * 64 + jq * 16;
    *(uint4*)dst = *(uint4*)hp;
    *(uint4*)(dst + 8) = *(uint4*)(hp + 8);
}

// ---------------- fused agg2 + mm2 (4-t chunks, dinv folded, MLP8) ----------------
__global__ void __launch_bounds__(256) agg2mm2_kernel(const float* __restrict__ W2,
                                                      const float* __restrict__ b2) {
    __shared__ float W2s[H * H];
    __shared__ float b2s[H];
    __shared__ float zs[8][4][64];
    int tid = threadIdx.x, w = tid >> 5, lane = tid & 31;
    for (int i = tid; i < H * H; i += 256) W2s[i] = W2[i];
    if (tid < H) b2s[tid] = b2[tid];
    int n = blockIdx.x * 8 + w;
    int q = blockIdx.y;
    float dn = d_dinv[n];
    const uint* h1u = (const uint*)d_h1;
    float acc[4][2];
    #pragma unroll
    for (int tt = 0; tt < 4; tt++) {
        uint u = h1u[((size_t)(q * 4 + tt) * NN + n) * 32 + lane];
        float2 p = __half22float2(*(__half2*)&u);
        acc[tt][0] = p.x; acc[tt][1] = p.y;          // self term (h1 pre-scaled)
    }
    int e = d_rowptr[n], e1 = d_rowptr[n + 1];
    for (; e + 8 <= e1; e += 8) {
        int si[8];
        #pragma unroll
        for (int u2 = 0; u2 < 8; u2++) si[u2] = d_csr[e + u2];
        #pragma unroll
        for (int u2 = 0; u2 < 8; u2++) {
            #pragma unroll
            for (int tt = 0; tt < 4; tt++) {
                uint v = h1u[((size_t)(q * 4 + tt) * NN + si[u2]) * 32 + lane];
                float2 p = __half22float2(*(__half2*)&v);
                acc[tt][0] += p.x; acc[tt][1] += p.y;
            }
        }
    }
    for (; e < e1; e++) {
        int s = d_csr[e];
        #pragma unroll
        for (int tt = 0; tt < 4; tt++) {
            uint v = h1u[((size_t)(q * 4 + tt) * NN + s) * 32 + lane];
            float2 p = __half22float2(*(__half2*)&v);
            acc[tt][0] += p.x; acc[tt][1] += p.y;
        }
    }
    #pragma unroll
    for (int tt = 0; tt < 4; tt++) {
        zs[w][tt][lane * 2] = acc[tt][0] * dn;
        zs[w][tt][lane * 2 + 1] = acc[tt][1] * dn;
    }
    __syncthreads();
    int n2 = tid >> 5, t2 = (lane >> 3) & 3, j0 = (lane & 7) * 8;
    float o[8];
    #pragma unroll
    for (int jj = 0; jj < 8; jj++) o[jj] = b2s[j0 + jj];
    #pragma unroll 8
    for (int k = 0; k < 64; k++) {
        float zv = zs[n2][t2][k];
        float4 w0 = *(float4*)(W2s + k * 64 + j0);
        float4 w1 = *(float4*)(W2s + k * 64 + j0 + 4);
        o[0] = fmaf(zv, w0.x, o[0]); o[1] = fmaf(zv, w0.y, o[1]);
        o[2] = fmaf(zv, w0.z, o[2]); o[3] = fmaf(zv, w0.w, o[3]);
        o[4] = fmaf(zv, w1.x, o[4]); o[5] = fmaf(zv, w1.y, o[5]);
        o[6] = fmaf(zv, w1.z, o[6]); o[7] = fmaf(zv, w1.w, o[7]);
    }
    ushort hh[8], hl[8];
    #pragma unroll
    for (int jj = 0; jj < 8; jj++) {
        float v = fmaxf(o[jj], 0.0f);
        __nv_bfloat16 hi = __float2bfloat16_rn(v);
        __nv_bfloat16 lo = __float2bfloat16_rn(v - __bfloat162float(hi));
        hh[jj] = __bfloat16_as_ushort(hi);
        hl[jj] = __bfloat16_as_ushort(lo);
    }
    int ng = blockIdx.x * 8 + n2;
    size_t base = ((size_t)(q * 4 + t2) * NPAD + ng) * 64 + j0;
    *(uint4*)(d_h2h + base) = *(uint4*)hh;
    *(uint4*)(d_h2l + base) = *(uint4*)hl;
}

// ---------------- A staging: cp.async into smem buf ----------------
__device__ __forceinline__ void stageA(
    char* smem, uint32_t sb, int buf, int tile, bool zero_h,
    const __nv_bfloat16* h2h, const __nv_bfloat16* h2l,
    const __nv_bfloat16* hhp, const __nv_bfloat16* hlp, int tid) {
    int row0 = tile * 64;
    uint32_t bufb = sb + AOFF + buf * 51200;
    #pragma unroll
    for (int it = 0; it < 12; it++) {
        int i = tid + it * 256;
        int p = i / 1536;
        int rem = i - p * 1536;
        int row = rem / 24, u = rem % 24;
        uint32_t dst = bufb + p * 25600 + row * 400 + u * 16;
        if (u < 8) {
            cp16(dst, (p ? h2l : h2h) + (size_t)(row0 + row) * 64 + u * 8);
        } else if (!zero_h) {
            cp16(dst, (p ? hlp : hhp) + (size_t)(row0 + row) * 128 + (u - 8) * 8);
        } else {
            *(uint4*)(smem + AOFF + buf * 51200 + p * 25600 + row * 400 + u * 16) =
                make_uint4(0, 0, 0, 0);
        }
    }
    asm volatile("cp.async.commit_group;" ::: "memory");
}

// ---------------- persistent LSTM: all 24 steps, one kernel ----------------
__global__ void __launch_bounds__(256, 1) lstm_persist(const float* __restrict__ bih,
                                                       const float* __restrict__ bhh) {
    extern __shared__ char smem[];
    float* bs = (float*)smem;
    uint32_t sb = smem_u32(smem);
    const int tid = threadIdx.x, lane = tid & 31, wid = tid >> 5;
    const int nb = blockIdx.x & 3;
    const int gidx = blockIdx.x >> 2;
    const int cnt = (gidx < NTILES64 - NGRP * 21) ? 22 : 21;

    for (int j = tid; j < 512; j += 256) bs[j] = bih[j] + bhh[j];
    for (int i = tid; i < 2 * 128 * 24; i += 256) {
        int p = i / (128 * 24);
        int rem = i - p * (128 * 24);
        int col = rem / 24, u = rem % 24;
        uint4 v = d_Bp[(size_t)(p * 512 + nb * 128 + col) * 24 + u];
        *(uint4*)(smem + BOFF + p * 51200 + col * 400 + u * 16) = v;
    }
    __syncthreads();

    const int wm = wid & 1;
    const int wn = wid >> 1;
    const int q = lane >> 3, r8 = lane & 7;
    const uint32_t aRowOff = (uint32_t)((wm * 32 + (q & 1) * 8 + r8) * 400 + ((q >> 1) * 8) * 2);
    const uint32_t bRowBase = (uint32_t)((wn * 32 + (q >> 1) * 8 + r8) * 400 + (q & 1) * 16);
    const int gq = lane >> 2, tq = lane & 3;

    for (int t = 0; t < T_STEPS; t++) {
        const __nv_bfloat16* h2h = d_h2h + (size_t)t * NPAD * 64;
        const __nv_bfloat16* h2l = d_h2l + (size_t)t * NPAD * 64;
        const __nv_bfloat16* hhp = (t & 1) ? d_hh1 : d_hh0;
        const __nv_bfloat16* hlp = (t & 1) ? d_hl1 : d_hl0;
        __nv_bfloat16* hhn = (t & 1) ? d_hh0 : d_hh1;
        __nv_bfloat16* hln = (t & 1) ? d_hl0 : d_hl1;
        const bool z = (t == 0);

        stageA(smem, sb, 0, gidx, z, h2h, h2l, hhp, hlp, tid);

        for (int k = 0; k < cnt; k++) {
            int tile = gidx + k * NGRP;
            if (k + 1 < cnt) {
                stageA(smem, sb, (k + 1) & 1, gidx + (k + 1) * NGRP, z, h2h, h2l, hhp, hlp, tid);
                asm volatile("cp.async.wait_group 1;" ::: "memory");
            } else {
                asm volatile("cp.async.wait_group 0;" ::: "memory");
            }
            __syncthreads();

            float acc[2][4][4];
            #pragma unroll
            for (int mi = 0; mi < 2; mi++)
                #pragma unroll
                for (int nt = 0; nt < 4; nt++)
                    #pragma unroll
                    for (int r = 0; r < 4; r++) acc[mi][nt][r] = 0.0f;

            uint32_t abufb = sb + AOFF + (k & 1) * 51200;
            #pragma unroll 1
            for (int pass = 0; pass < 3; pass++) {
                uint32_t aB = abufb + (pass == 2 ? 25600 : 0) + aRowOff;
                uint32_t bB = sb + BOFF + (pass == 1 ? 51200 : 0) + bRowBase;
                #pragma unroll 1
                for (int ks = 0; ks < 12; ks++) {
                    uint32_t a[2][4];
                    ldsm4(a[0], aB + ks * 32);
                    ldsm4(a[1], aB + 16 * 400 + ks * 32);
                    uint32_t b[4][2];
                    {
                        uint32_t t4[4];
                        ldsm4(t4, bB + ks * 32);
                        b[0][0] = t4[0]; b[0][1] = t4[1];
                        b[1][0] = t4[2]; b[1][1] = t4[3];
                    }
                    {
                        uint32_t t4[4];
                        ldsm4(t4, bB + 16 * 400 + ks * 32);
                        b[2][0] = t4[0]; b[2][1] = t4[1];
                        b[3][0] = t4[2]; b[3][1] = t4[3];
                    }
                    #pragma unroll
                    for (int mi = 0; mi < 2; mi++)
                        #pragma unroll
                        for (int nt = 0; nt < 4; nt++)
                            mma16816(acc[mi][nt], a[mi], b[nt]);
                }
            }

            int row0 = tile * 64;
            #pragma unroll
            for (int mi = 0; mi < 2; mi++) {
                #pragma unroll
                for (int h = 0; h < 2; h++) {
                    int rl = wm * 32 + mi * 16 + h * 8 + gq;
                    int n = row0 + rl;
                    float* cptr = d_cs2 + ((size_t)nb * NPAD + n) * 32 + wn * 8 + tq * 2;
                    float2 cp = z ? make_float2(0.0f, 0.0f) : *(float2*)cptr;
                    uint hiPack = 0, loPack = 0;
                    #pragma unroll
                    for (int p = 0; p < 2; p++) {
                        int jgl = nb * 32 + wn * 8 + tq * 2 + p;
                        int ci = h * 2 + p;
                        float gi = acc[mi][0][ci] + bs[jgl];
                        float gf = acc[mi][1][ci] + bs[128 + jgl];
                        float gG = acc[mi][2][ci] + bs[256 + jgl];
                        float go = acc[mi][3][ci] + bs[384 + jgl];
                        float cold = p ? cp.y : cp.x;
                        float cn = sigf(gf) * cold + sigf(gi) * tanhfast(gG);
                        float hv = sigf(go) * tanhfast(cn);
                        if (p) cp.y = cn; else cp.x = cn;
                        __nv_bfloat16 hi = __float2bfloat16_rn(hv);
                        __nv_bfloat16 lo = __float2bfloat16_rn(hv - __bfloat162float(hi));
                        hiPack |= ((uint)__bfloat16_as_ushort(hi)) << (16 * p);
                        loPack |= ((uint)__bfloat16_as_ushort(lo)) << (16 * p);
                    }
                    *(float2*)cptr = cp;
                    size_t hb = (size_t)n * 128 + nb * 32 + wn * 8 + tq * 2;
                    *(uint*)(hhn + hb) = hiPack;
                    *(uint*)(hln + hb) = loPack;
                }
            }
            __syncthreads();
        }

        if (t < T_STEPS - 1) {
            __syncthreads();
            if (tid == 0) {
                __threadfence();
                atomicAdd(&d_bar, 1u);
                unsigned target = (unsigned)NCTAS * (unsigned)(t + 1);
                unsigned v;
                do {
                    asm volatile("ld.acquire.gpu.global.u32 %0, [%1];"
                                 : "=r"(v) : "l"(&d_bar) : "memory");
                    if (v < target) asm volatile("nanosleep.u32 64;");
                } while (v < target);
            }
            __syncthreads();
        }
    }
}

// ---------------- FC head ----------------
__global__ void fc_kernel(const __nv_bfloat16* __restrict__ hh,
                          const __nv_bfloat16* __restrict__ hl,
                          const float* __restrict__ Wf1, const float* __restrict__ bf1,
                          const float* __restrict__ Wf2, const float* __restrict__ bf2,
                          float* __restrict__ out) {
    __shared__ float Ws[LH * 32];
    __shared__ float hsm[32][LH];
    int tid = threadIdx.x;
    for (int i = tid; i < LH * 32; i += 256) Ws[i] = Wf1[i];
    int n0 = blockIdx.x * 32;
    for (int i = tid; i < 32 * LH; i += 256) {
        int nl = i >> 7, k = i & 127;
        int n = n0 + nl;
        float v = 0.0f;
        if (n < NN) {
            size_t idx = (size_t)n * 128 + k;
            v = __bfloat162float(hh[idx]) + __bfloat162float(hl[idx]);
        }
        hsm[nl][k] = v;
    }
    __syncthreads();
    int w = tid >> 5, lane = tid & 31;
    float wf2 = Wf2[lane];
    float bb1 = bf1[lane];
    for (int r = 0; r < 4; r++) {
        int nl = w * 4 + r;
        int n = n0 + nl;
        float acc = bb1;
        #pragma unroll
        for (int k = 0; k < LH; k++) acc = fmaf(hsm[nl][k], Ws[k * 32 + lane], acc);
        acc = fmaxf(acc, 0.0f) * wf2;
        #pragma unroll
        for (int off = 16; off > 0; off >>= 1)
            acc += __shfl_down_sync(0xffffffffu, acc, off);
        if (lane == 0 && n < NN) out[n] = acc + bf2[0];
    }
}

// ---------------- launcher ----------------
extern "C" void kernel_launch(void* const* d_in, const int* in_sizes, int n_in,
                              void* d_out, int out_size) {
    const float* x_seq = (const float*)d_in[0];
    const int*   ei    = (const int*)d_in[1];
    const float* W1    = (const float*)d_in[2];
    const float* b1    = (const float*)d_in[3];
    const float* W2    = (const float*)d_in[4];
    const float* b2    = (const float*)d_in[5];
    const float* Wih   = (const float*)d_in[6];
    const float* Whh   = (const float*)d_in[7];
    const float* bih   = (const float*)d_in[8];
    const float* bhh   = (const float*)d_in[9];
    const float* Wf1   = (const float*)d_in[10];
    const float* bf1   = (const float*)d_in[11];
    const float* Wf2   = (const float*)d_in[12];
    const float* bf2   = (const float*)d_in[13];
    float* out = (float*)d_out;

    cudaFuncSetAttribute(lstm_persist, cudaFuncAttributeMaxDynamicSharedMemorySize,
                         PERSIST_SMEM);

    void* degp;
    cudaGetSymbolAddress(&degp, d_deg);
    cudaMemsetAsync(degp, 0, NN * sizeof(int));

    __nv_bfloat16 *hh0, *hl0;
    cudaGetSymbolAddress((void**)&hh0, d_hh0);
    cudaGetSymbolAddress((void**)&hl0, d_hl0);

    deg_kernel<<<(EE + 255) / 256, 256>>>(ei);
    dinv_scan_kernel<<<SCAN_NB, 512>>>();
    scan_add2_kernel<<<(NN + 255) / 256, 256>>>();
    fused_fill_kernel<<<25096, 256>>>(ei, x_seq, Wih, Whh);
    agg1mm1_kernel<<<dim3(NN / 8, 3), 256>>>(W1, b1);
    agg2mm2_kernel<<<dim3(NN / 8, 6), 256>>>(W2, b2);
    lstm_persist<<<NCTAS, 256, PERSIST_SMEM>>>(bih, bhh);
    fc_kernel<<<(NN + 31) / 32, 256>>>(hh0, hl0, Wf1, bf1, Wf2, bf2, out);
}

// round 8
// speedup vs baseline: 1.9770x; 1.3420x over previous
#include <cuda_runtime.h>
#include <cuda_bf16.h>
#include <cuda_fp16.h>
#include <math.h>
#include <stdint.h>

#define T_STEPS 24
#define NN 50000
#define NPAD 50048
#define EE 1600000
#define F 16
#define H 64
#define LH 128
#define SCAN_NB 98

#define NTILES128 391           // NPAD/128
#define NCTAS 148
#define NGRP 37                 // CTA groups per nb (148/4)

// persistent-kernel smem layout
#define BIAS_OFF 0              // 512 floats = 2048 B
#define BOFF 2048               // B hi+lo fp16: 2 * 128 * 400 = 102400
#define AOFF (2048 + 102400)    // A double buffer: 2 * 51200 (128 rows x 400 B)
#define PERSIST_SMEM (AOFF + 2 * 51200)   // 206848

// ---------------- helpers ----------------
__device__ __forceinline__ uint32_t smem_u32(const void* p) {
    uint32_t a;
    asm("{ .reg .u64 t; cvta.to.shared.u64 t, %1; cvt.u32.u64 %0, t; }" : "=r"(a) : "l"(p));
    return a;
}
__device__ __forceinline__ void ldsm4(uint32_t* r, uint32_t addr) {
    asm volatile("ldmatrix.sync.aligned.m8n8.x4.shared.b16 {%0,%1,%2,%3}, [%4];"
                 : "=r"(r[0]), "=r"(r[1]), "=r"(r[2]), "=r"(r[3]) : "r"(addr));
}
__device__ __forceinline__ void mma16816(float* c, const uint32_t* a, const uint32_t* b) {
    asm volatile(
        "mma.sync.aligned.m16n8k16.row.col.f32.f16.f16.f32 "
        "{%0,%1,%2,%3}, {%4,%5,%6,%7}, {%8,%9}, {%0,%1,%2,%3};"
        : "+f"(c[0]), "+f"(c[1]), "+f"(c[2]), "+f"(c[3])
        : "r"(a[0]), "r"(a[1]), "r"(a[2]), "r"(a[3]), "r"(b[0]), "r"(b[1]));
}
__device__ __forceinline__ void cp16(uint32_t dst, const void* src) {
    asm volatile("cp.async.cg.shared.global [%0], [%1], 16;" :: "r"(dst), "l"(src));
}
__device__ __forceinline__ float tanha(float x) {
    float r;
    asm("tanh.approx.f32 %0, %1;" : "=f"(r) : "f"(x));
    return r;
}
__device__ __forceinline__ float sigt(float x) {
    return fmaf(tanha(0.5f * x), 0.5f, 0.5f);
}

// ---------------- scratch ----------------
__device__ int   d_deg[NN];
__device__ int   d_rowptr[NN + 1];
__device__ int   d_cursor[NN];
__device__ int   d_csr[EE];
__device__ int   d_blocksum[128];
__device__ float d_dinv[NN];
__device__ unsigned d_bar;
__device__ __half d_xh[19200000];                 // [n][t*16+c]  (x * dinv[n])
__device__ __half d_h1[76800000];                 // [t][n][64]   (h1 * dinv[n])
__device__ __half d_h2[76873728];                 // [t][NPAD][64] fp16
__device__ __half d_hs0[6406144];                 // [NPAD][128] fp16 h
__device__ __half d_hs1[6406144];
__device__ float d_cs2[6406144];                  // [nb][NPAD][32]
__device__ uint4 d_Bp[2 * 512 * 24];              // fp16 hi/lo weights, reordered cols

// ---------------- CSR build ----------------
__global__ void deg_kernel(const int* __restrict__ ei) {
    int e = blockIdx.x * 256 + threadIdx.x;
    if (e < EE) atomicAdd(&d_deg[ei[EE + e]], 1);
}
__global__ void dinv_scan_kernel() {
    __shared__ int s[512];
    int tid = threadIdx.x;
    int i = blockIdx.x * 512 + tid;
    if (i == 0) d_bar = 0;
    int v = (i < NN) ? d_deg[i] : 0;
    if (i < NN) d_dinv[i] = rsqrtf((float)v + 1.0f);
    s[tid] = v;
    __syncthreads();
    #pragma unroll
    for (int off = 1; off < 512; off <<= 1) {
        int t = (tid >= off) ? s[tid - off] : 0;
        __syncthreads();
        s[tid] += t;
        __syncthreads();
    }
    if (i < NN) d_rowptr[i + 1] = s[tid];
    if (tid == 511) d_blocksum[blockIdx.x] = s[511];
}
__global__ void scan_add2_kernel() {
    __shared__ int soff;
    int sbk = blockIdx.x >> 1;
    if (threadIdx.x == 0) {
        int o = 0;
        for (int j = 0; j < sbk; j++) o += d_blocksum[j];
        soff = o;
    }
    __syncthreads();
    int i = blockIdx.x * 256 + threadIdx.x;
    if (i == 0) { d_rowptr[0] = 0; d_cursor[0] = 0; }
    if (i < NN) {
        int v = d_rowptr[i + 1] + soff;
        d_rowptr[i + 1] = v;
        if (i + 1 < NN) d_cursor[i + 1] = v;
    }
}

// ---------------- fused fill: csr_fill + xprep + bprep ----------------
// B reorder: cg in [0,512): nb=cg>>7, c=cg&127: wn=(c>>6), g=(c>>4)&3, jh=(c>>3)&1, s=c&7
// jg = nb*32 + wn*16 + jh*8 + s ; G = g*128 + jg
__global__ void fused_fill_kernel(const int* __restrict__ ei,
                                  const float* __restrict__ x_seq,
                                  const float* __restrict__ Wih,
                                  const float* __restrict__ Whh) {
    int b = blockIdx.x;
    if (b < 6250) {
        int e = b * 256 + threadIdx.x;
        int s = ei[e];
        int d = ei[EE + e];
        int idx = atomicAdd(&d_cursor[d], 1);
        d_csr[idx] = s;
    } else if (b < 25000) {
        int id = (b - 6250) * 256 + threadIdx.x;
        if (id >= NN * 96) return;
        int n = id / 96, r = id % 96;
        int t = r >> 2, c4 = r & 3;
        float dn = d_dinv[n];
        float4 v = *(const float4*)(x_seq + ((size_t)t * NN + n) * F + c4 * 4);
        __half h[4] = {__float2half_rn(v.x * dn), __float2half_rn(v.y * dn),
                       __float2half_rn(v.z * dn), __float2half_rn(v.w * dn)};
        *(uint2*)(d_xh + (size_t)n * 384 + r * 4) = *(uint2*)h;
    } else {
        int id = (b - 25000) * 256 + threadIdx.x;
        if (id >= 2 * 512 * 24) return;
        int p = id / (512 * 24);
        int rem = id - p * (512 * 24);
        int cg = rem / 24, u = rem % 24;
        int nb = cg >> 7, c = cg & 127;
        int wn = c >> 6, g = (c >> 4) & 3, jh = (c >> 3) & 1, s = c & 7;
        int jg = nb * 32 + wn * 16 + jh * 8 + s;
        int G = g * 128 + jg;
        union { __half h[8]; uint4 q; } up;
        #pragma unroll
        for (int e = 0; e < 8; e++) {
            int k = u * 8 + e;
            float v = (k < 64) ? Wih[G * 64 + k] : Whh[G * 128 + (k - 64)];
            __half hi = __float2half_rn(v);
            up.h[e] = p ? __float2half_rn(v - __half2float(hi)) : hi;
        }
        d_Bp[(size_t)(p * 512 + cg) * 24 + u] = up.q;
    }
}

// ---------------- fused agg1 + mm1 (8-t chunks, dinv folded, MLP8) ----------------
__global__ void __launch_bounds__(256) agg1mm1_kernel(const float* __restrict__ W1,
                                                      const float* __restrict__ b1) {
    __shared__ float W1s[F * H];
    __shared__ float b1s[H];
    __shared__ float ys[8][128];
    int tid = threadIdx.x, w = tid >> 5, lane = tid & 31;
    for (int i = tid; i < F * H; i += 256) W1s[i] = W1[i];
    if (tid < H) b1s[tid] = b1[tid];
    int n = blockIdx.x * 8 + w;
    int q = blockIdx.y;
    float dn = d_dinv[n];
    const uint2* xr = (const uint2*)d_xh;
    uint2 u = xr[(size_t)n * 96 + q * 32 + lane];
    float2 p0 = __half22float2(*(__half2*)&u.x);
    float2 p1 = __half22float2(*(__half2*)&u.y);
    float a0 = p0.x, a1 = p0.y, a2 = p1.x, a3 = p1.y;
    int e = d_rowptr[n], e1 = d_rowptr[n + 1];
    for (; e + 8 <= e1; e += 8) {
        int si[8];
        #pragma unroll
        for (int k = 0; k < 8; k++) si[k] = d_csr[e + k];
        #pragma unroll
        for (int k = 0; k < 8; k++) {
            uint2 v = xr[(size_t)si[k] * 96 + q * 32 + lane];
            float2 q0 = __half22float2(*(__half2*)&v.x);
            float2 q1 = __half22float2(*(__half2*)&v.y);
            a0 += q0.x; a1 += q0.y; a2 += q1.x; a3 += q1.y;
        }
    }
    for (; e < e1; e++) {
        int s = d_csr[e];
        uint2 v = xr[(size_t)s * 96 + q * 32 + lane];
        float2 q0 = __half22float2(*(__half2*)&v.x);
        float2 q1 = __half22float2(*(__half2*)&v.y);
        a0 += q0.x; a1 += q0.y; a2 += q1.x; a3 += q1.y;
    }
    ys[w][lane * 4 + 0] = a0 * dn; ys[w][lane * 4 + 1] = a1 * dn;
    ys[w][lane * 4 + 2] = a2 * dn; ys[w][lane * 4 + 3] = a3 * dn;
    __syncthreads();
    int n2 = tid >> 5, t2 = lane >> 2, jq = lane & 3;
    int ng = blockIdx.x * 8 + n2;
    float dscale = d_dinv[ng];
    float yv[16];
    #pragma unroll
    for (int k = 0; k < 16; k++) yv[k] = ys[n2][t2 * 16 + k];
    float o[16];
    #pragma unroll
    for (int jj = 0; jj < 16; jj++) o[jj] = b1s[jq * 16 + jj];
    #pragma unroll
    for (int k = 0; k < 16; k++)
        #pragma unroll
        for (int jj = 0; jj < 16; jj++)
            o[jj] = fmaf(yv[k], W1s[k * 64 + jq * 16 + jj], o[jj]);
    __half hp[16];
    #pragma unroll
    for (int jj = 0; jj < 16; jj++)
        hp[jj] = __float2half_rn(fmaxf(o[jj], 0.0f) * dscale);
    int tg = q * 8 + t2;
    __half* dst = d_h1 + ((size_t)tg * NN + ng) * 64 + jq * 16;
    *(uint4*)dst = *(uint4*)hp;
    *(uint4*)(dst + 8) = *(uint4*)(hp + 8);
}

// ---------------- fused agg2 + mm2 (4-t chunks, dinv folded, MLP8) ----------------
__global__ void __launch_bounds__(256) agg2mm2_kernel(const float* __restrict__ W2,
                                                      const float* __restrict__ b2) {
    __shared__ float W2s[H * H];
    __shared__ float b2s[H];
    __shared__ float zs[8][4][64];
    int tid = threadIdx.x, w = tid >> 5, lane = tid & 31;
    for (int i = tid; i < H * H; i += 256) W2s[i] = W2[i];
    if (tid < H) b2s[tid] = b2[tid];
    int n = blockIdx.x * 8 + w;
    int q = blockIdx.y;
    float dn = d_dinv[n];
    const uint* h1u = (const uint*)d_h1;
    float acc[4][2];
    #pragma unroll
    for (int tt = 0; tt < 4; tt++) {
        uint u = h1u[((size_t)(q * 4 + tt) * NN + n) * 32 + lane];
        float2 p = __half22float2(*(__half2*)&u);
        acc[tt][0] = p.x; acc[tt][1] = p.y;
    }
    int e = d_rowptr[n], e1 = d_rowptr[n + 1];
    for (; e + 8 <= e1; e += 8) {
        int si[8];
        #pragma unroll
        for (int u2 = 0; u2 < 8; u2++) si[u2] = d_csr[e + u2];
        #pragma unroll
        for (int u2 = 0; u2 < 8; u2++) {
            #pragma unroll
            for (int tt = 0; tt < 4; tt++) {
                uint v = h1u[((size_t)(q * 4 + tt) * NN + si[u2]) * 32 + lane];
                float2 p = __half22float2(*(__half2*)&v);
                acc[tt][0] += p.x; acc[tt][1] += p.y;
            }
        }
    }
    for (; e < e1; e++) {
        int s = d_csr[e];
        #pragma unroll
        for (int tt = 0; tt < 4; tt++) {
            uint v = h1u[((size_t)(q * 4 + tt) * NN + s) * 32 + lane];
            float2 p = __half22float2(*(__half2*)&v);
            acc[tt][0] += p.x; acc[tt][1] += p.y;
        }
    }
    #pragma unroll
    for (int tt = 0; tt < 4; tt++) {
        zs[w][tt][lane * 2] = acc[tt][0] * dn;
        zs[w][tt][lane * 2 + 1] = acc[tt][1] * dn;
    }
    __syncthreads();
    int n2 = tid >> 5, t2 = (lane >> 3) & 3, j0 = (lane & 7) * 8;
    float o[8];
    #pragma unroll
    for (int jj = 0; jj < 8; jj++) o[jj] = b2s[j0 + jj];
    #pragma unroll 8
    for (int k = 0; k < 64; k++) {
        float zv = zs[n2][t2][k];
        float4 w0 = *(float4*)(W2s + k * 64 + j0);
        float4 w1 = *(float4*)(W2s + k * 64 + j0 + 4);
        o[0] = fmaf(zv, w0.x, o[0]); o[1] = fmaf(zv, w0.y, o[1]);
        o[2] = fmaf(zv, w0.z, o[2]); o[3] = fmaf(zv, w0.w, o[3]);
        o[4] = fmaf(zv, w1.x, o[4]); o[5] = fmaf(zv, w1.y, o[5]);
        o[6] = fmaf(zv, w1.z, o[6]); o[7] = fmaf(zv, w1.w, o[7]);
    }
    __half hp[8];
    #pragma unroll
    for (int jj = 0; jj < 8; jj++)
        hp[jj] = __float2half_rn(fmaxf(o[jj], 0.0f));
    int ng = blockIdx.x * 8 + n2;
    size_t base = ((size_t)(q * 4 + t2) * NPAD + ng) * 64 + j0;
    *(uint4*)(d_h2 + base) = *(uint4*)hp;
}

// ---------------- A staging: single fp16 plane, cp.async ----------------
__device__ __forceinline__ void stageA(
    char* smem, uint32_t sb, int buf, int tile, bool zero_h,
    const __half* h2, const __half* hp, int tid) {
    int row0 = tile * 128;
    uint32_t bufb = sb + AOFF + buf * 51200;
    #pragma unroll
    for (int it = 0; it < 12; it++) {
        int i = tid + it * 256;                  // 0..3071
        int row = i / 24, u = i % 24;
        uint32_t dst = bufb + row * 400 + u * 16;
        if (u < 8) {
            cp16(dst, h2 + (size_t)(row0 + row) * 64 + u * 8);
        } else if (!zero_h) {
            cp16(dst, hp + (size_t)(row0 + row) * 128 + (u - 8) * 8);
        } else {
            *(uint4*)(smem + AOFF + buf * 51200 + row * 400 + u * 16) =
                make_uint4(0, 0, 0, 0);
        }
    }
    asm volatile("cp.async.commit_group;" ::: "memory");
}

// ---------------- persistent LSTM: 2-pass fp16, M=128 tiles ----------------
__global__ void __launch_bounds__(256, 1) lstm_persist(const float* __restrict__ bih,
                                                       const float* __restrict__ bhh) {
    extern __shared__ char smem[];
    float* bs = (float*)smem;
    uint32_t sb = smem_u32(smem);
    const int tid = threadIdx.x, lane = tid & 31, wid = tid >> 5;
    const int nb = blockIdx.x & 3;
    const int gidx = blockIdx.x >> 2;          // 0..36
    const int cnt = (gidx < NTILES128 - NGRP * 10) ? 11 : 10;   // 391 = 21*11 + 16*10

    for (int j = tid; j < 512; j += 256) bs[j] = bih[j] + bhh[j];
    for (int i = tid; i < 2 * 128 * 24; i += 256) {
        int p = i / (128 * 24);
        int rem = i - p * (128 * 24);
        int col = rem / 24, u = rem % 24;
        uint4 v = d_Bp[(size_t)(p * 512 + nb * 128 + col) * 24 + u];
        *(uint4*)(smem + BOFF + p * 51200 + col * 400 + u * 16) = v;
    }
    __syncthreads();

    const int wm = wid & 3;                    // row quarter (32 rows)
    const int wn = wid >> 2;                   // col half (64 cols)
    const int q = lane >> 3, r8 = lane & 7;
    const uint32_t aRowOff = (uint32_t)((wm * 32 + (q & 1) * 8 + r8) * 400 + ((q >> 1) * 8) * 2);
    const uint32_t bRowBase = (uint32_t)((wn * 64 + (q >> 1) * 8 + r8) * 400 + (q & 1) * 16);
    const int gq = lane >> 2, tq = lane & 3;

    for (int t = 0; t < T_STEPS; t++) {
        const __half* h2 = d_h2 + (size_t)t * NPAD * 64;
        const __half* hp = (t & 1) ? d_hs1 : d_hs0;
        __half* hn = (t & 1) ? d_hs0 : d_hs1;
        const bool z = (t == 0);

        stageA(smem, sb, 0, gidx, z, h2, hp, tid);

        for (int k = 0; k < cnt; k++) {
            int tile = gidx + k * NGRP;
            if (k + 1 < cnt) {
                stageA(smem, sb, (k + 1) & 1, gidx + (k + 1) * NGRP, z, h2, hp, tid);
                asm volatile("cp.async.wait_group 1;" ::: "memory");
            } else {
                asm volatile("cp.async.wait_group 0;" ::: "memory");
            }
            __syncthreads();

            float acc[2][8][4];
            #pragma unroll
            for (int mi = 0; mi < 2; mi++)
                #pragma unroll
                for (int nt = 0; nt < 8; nt++)
                    #pragma unroll
                    for (int r = 0; r < 4; r++) acc[mi][nt][r] = 0.0f;

            uint32_t abufb = sb + AOFF + (k & 1) * 51200;
            #pragma unroll 1
            for (int pass = 0; pass < 2; pass++) {
                uint32_t aB = abufb + aRowOff;
                uint32_t bB = sb + BOFF + (pass ? 51200 : 0) + bRowBase;
                #pragma unroll 1
                for (int ks = 0; ks < 12; ks++) {
                    uint32_t a[2][4];
                    ldsm4(a[0], aB + ks * 32);
                    ldsm4(a[1], aB + 16 * 400 + ks * 32);
                    uint32_t b[8][2];
                    #pragma unroll
                    for (int pr = 0; pr < 4; pr++) {
                        uint32_t t4[4];
                        ldsm4(t4, bB + pr * (16 * 400) + ks * 32);
                        b[2 * pr][0] = t4[0]; b[2 * pr][1] = t4[1];
                        b[2 * pr + 1][0] = t4[2]; b[2 * pr + 1][1] = t4[3];
                    }
                    #pragma unroll
                    for (int mi = 0; mi < 2; mi++)
                        #pragma unroll
                        for (int nt = 0; nt < 8; nt++)
                            mma16816(acc[mi][nt], a[mi], b[nt]);
                }
            }

            // fused LSTM epilogue
            int row0 = tile * 128;
            #pragma unroll
            for (int mi = 0; mi < 2; mi++) {
                #pragma unroll
                for (int h = 0; h < 2; h++) {
                    int rl = wm * 32 + mi * 16 + h * 8 + gq;
                    int n = row0 + rl;
                    #pragma unroll
                    for (int jh = 0; jh < 2; jh++) {
                        int jl0 = wn * 16 + jh * 8 + 2 * tq;
                        float* cptr = d_cs2 + ((size_t)nb * NPAD + n) * 32 + jl0;
                        float2 cp = z ? make_float2(0.0f, 0.0f) : *(float2*)cptr;
                        __half hout[2];
                        #pragma unroll
                        for (int p = 0; p < 2; p++) {
                            int jgl = nb * 32 + jl0 + p;
                            int ci = h * 2 + p;
                            float gi = acc[mi][0 + jh][ci] + bs[jgl];
                            float gf = acc[mi][2 + jh][ci] + bs[128 + jgl];
                            float gG = acc[mi][4 + jh][ci] + bs[256 + jgl];
                            float go = acc[mi][6 + jh][ci] + bs[384 + jgl];
                            float cold = p ? cp.y : cp.x;
                            float cn = sigt(gf) * cold + sigt(gi) * tanha(gG);
                            float hv = sigt(go) * tanha(cn);
                            if (p) cp.y = cn; else cp.x = cn;
                            hout[p] = __float2half_rn(hv);
                        }
                        *(float2*)cptr = cp;
                        *(uint*)(hn + (size_t)n * 128 + nb * 32 + jl0) = *(uint*)hout;
                    }
                }
            }
            __syncthreads();
        }

        if (t < T_STEPS - 1) {
            __syncthreads();
            if (tid == 0) {
                __threadfence();
                atomicAdd(&d_bar, 1u);
                unsigned target = (unsigned)NCTAS * (unsigned)(t + 1);
                unsigned v;
                do {
                    asm volatile("ld.acquire.gpu.global.u32 %0, [%1];"
                                 : "=r"(v) : "l"(&d_bar) : "memory");
                    if (v < target) asm volatile("nanosleep.u32 64;");
                } while (v < target);
            }
            __syncthreads();
        }
    }
}

// ---------------- FC head ----------------
__global__ void fc_kernel(const __half* __restrict__ hfin,
                          const float* __restrict__ Wf1, const float* __restrict__ bf1,
                          const float* __restrict__ Wf2, const float* __restrict__ bf2,
                          float* __restrict__ out) {
    __shared__ float Ws[LH * 32];
    __shared__ float hsm[32][LH];
    int tid = threadIdx.x;
    for (int i = tid; i < LH * 32; i += 256) Ws[i] = Wf1[i];
    int n0 = blockIdx.x * 32;
    for (int i = tid; i < 32 * LH; i += 256) {
        int nl = i >> 7, k = i & 127;
        int n = n0 + nl;
        hsm[nl][k] = (n < NN) ? __half2float(hfin[(size_t)n * 128 + k]) : 0.0f;
    }
    __syncthreads();
    int w = tid >> 5, lane = tid & 31;
    float wf2 = Wf2[lane];
    float bb1 = bf1[lane];
    for (int r = 0; r < 4; r++) {
        int nl = w * 4 + r;
        int n = n0 + nl;
        float acc = bb1;
        #pragma unroll
        for (int k = 0; k < LH; k++) acc = fmaf(hsm[nl][k], Ws[k * 32 + lane], acc);
        acc = fmaxf(acc, 0.0f) * wf2;
        #pragma unroll
        for (int off = 16; off > 0; off >>= 1)
            acc += __shfl_down_sync(0xffffffffu, acc, off);
        if (lane == 0 && n < NN) out[n] = acc + bf2[0];
    }
}

// ---------------- launcher ----------------
extern "C" void kernel_launch(void* const* d_in, const int* in_sizes, int n_in,
                              void* d_out, int out_size) {
    const float* x_seq = (const float*)d_in[0];
    const int*   ei    = (const int*)d_in[1];
    const float* W1    = (const float*)d_in[2];
    const float* b1    = (const float*)d_in[3];
    const float* W2    = (const float*)d_in[4];
    const float* b2    = (const float*)d_in[5];
    const float* Wih   = (const float*)d_in[6];
    const float* Whh   = (const float*)d_in[7];
    const float* bih   = (const float*)d_in[8];
    const float* bhh   = (const float*)d_in[9];
    const float* Wf1   = (const float*)d_in[10];
    const float* bf1   = (const float*)d_in[11];
    const float* Wf2   = (const float*)d_in[12];
    const float* bf2   = (const float*)d_in[13];
    float* out = (float*)d_out;

    cudaFuncSetAttribute(lstm_persist, cudaFuncAttributeMaxDynamicSharedMemorySize,
                         PERSIST_SMEM);

    void* degp;
    cudaGetSymbolAddress(&degp, d_deg);
    cudaMemsetAsync(degp, 0, NN * sizeof(int));

    __half* hs0;
    cudaGetSymbolAddress((void**)&hs0, d_hs0);

    deg_kernel<<<(EE + 255) / 256, 256>>>(ei);
    dinv_scan_kernel<<<SCAN_NB, 512>>>();
    scan_add2_kernel<<<(NN + 255) / 256, 256>>>();
    fused_fill_kernel<<<25096, 256>>>(ei, x_seq, Wih, Whh);
    agg1mm1_kernel<<<dim3(NN / 8, 3), 256>>>(W1, b1);
    agg2mm2_kernel<<<dim3(NN / 8, 6), 256>>>(W2, b2);
    lstm_persist<<<NCTAS, 256, PERSIST_SMEM>>>(bih, bhh);
    fc_kernel<<<(NN + 31) / 32, 256>>>(hs0, Wf1, bf1, Wf2, bf2, out);
}

// round 9
// speedup vs baseline: 2.2462x; 1.1362x over previous
#include <cuda_runtime.h>
#include <cuda_bf16.h>
#include <cuda_fp16.h>
#include <math.h>
#include <stdint.h>

#define T_STEPS 24
#define NN 50000
#define NPAD 50048
#define EE 1600000
#define F 16
#define H 64
#define LH 128
#define SCAN_NB 98

#define NTILES128 391           // NPAD/128
#define NCTAS 148
#define NGRP 37                 // CTA groups per nb (148/4)

// persistent-kernel smem layout (single-plane B)
#define BIAS_OFF 0              // 512 floats = 2048 B
#define BOFF 2048               // B fp16: 128 * 400 = 51200
#define AOFF (2048 + 51200)     // A double buffer: 2 * 51200 (128 rows x 400 B)
#define PERSIST_SMEM (AOFF + 2 * 51200)   // 155648

// ---------------- helpers ----------------
__device__ __forceinline__ uint32_t smem_u32(const void* p) {
    uint32_t a;
    asm("{ .reg .u64 t; cvta.to.shared.u64 t, %1; cvt.u32.u64 %0, t; }" : "=r"(a) : "l"(p));
    return a;
}
__device__ __forceinline__ void ldsm4(uint32_t* r, uint32_t addr) {
    asm volatile("ldmatrix.sync.aligned.m8n8.x4.shared.b16 {%0,%1,%2,%3}, [%4];"
                 : "=r"(r[0]), "=r"(r[1]), "=r"(r[2]), "=r"(r[3]) : "r"(addr));
}
__device__ __forceinline__ void mma16816(float* c, const uint32_t* a, const uint32_t* b) {
    asm volatile(
        "mma.sync.aligned.m16n8k16.row.col.f32.f16.f16.f32 "
        "{%0,%1,%2,%3}, {%4,%5,%6,%7}, {%8,%9}, {%0,%1,%2,%3};"
        : "+f"(c[0]), "+f"(c[1]), "+f"(c[2]), "+f"(c[3])
        : "r"(a[0]), "r"(a[1]), "r"(a[2]), "r"(a[3]), "r"(b[0]), "r"(b[1]));
}
__device__ __forceinline__ void cp16(uint32_t dst, const void* src) {
    asm volatile("cp.async.cg.shared.global [%0], [%1], 16;" :: "r"(dst), "l"(src));
}
__device__ __forceinline__ float tanha(float x) {
    float r;
    asm("tanh.approx.f32 %0, %1;" : "=f"(r) : "f"(x));
    return r;
}
__device__ __forceinline__ float sigt(float x) {
    return fmaf(tanha(0.5f * x), 0.5f, 0.5f);
}

// ---------------- scratch ----------------
__device__ int   d_deg[NN];
__device__ int   d_rowptr[NN + 1];
__device__ int   d_cursor[NN];
__device__ int   d_csr[EE];
__device__ int   d_blocksum[128];
__device__ float d_dinv[NN];
__device__ unsigned d_bar;
__device__ __half d_xh[19200000];                 // [n][t*16+c]  (x * dinv[n])
__device__ __half d_h1[76800000];                 // [t][n][64]   (h1 * dinv[n])
__device__ __half d_h2[76873728];                 // [t][NPAD][64] fp16
__device__ __half d_hs0[6406144];                 // [NPAD][128] fp16 h
__device__ __half d_hs1[6406144];
__device__ float d_cs2[6406144];                  // [nb][NPAD][32]
__device__ uint4 d_Bp[512 * 24];                  // fp16 weights, reordered cols

// ---------------- CSR build ----------------
__global__ void deg_kernel(const int* __restrict__ ei) {
    int e = blockIdx.x * 256 + threadIdx.x;
    if (e < EE) atomicAdd(&d_deg[ei[EE + e]], 1);
}
__global__ void dinv_scan_kernel() {
    __shared__ int s[512];
    int tid = threadIdx.x;
    int i = blockIdx.x * 512 + tid;
    if (i == 0) d_bar = 0;
    int v = (i < NN) ? d_deg[i] : 0;
    if (i < NN) d_dinv[i] = rsqrtf((float)v + 1.0f);
    s[tid] = v;
    __syncthreads();
    #pragma unroll
    for (int off = 1; off < 512; off <<= 1) {
        int t = (tid >= off) ? s[tid - off] : 0;
        __syncthreads();
        s[tid] += t;
        __syncthreads();
    }
    if (i < NN) d_rowptr[i + 1] = s[tid];
    if (tid == 511) d_blocksum[blockIdx.x] = s[511];
}
__global__ void scan_add2_kernel() {
    __shared__ int soff;
    int sbk = blockIdx.x >> 1;
    if (threadIdx.x == 0) {
        int o = 0;
        for (int j = 0; j < sbk; j++) o += d_blocksum[j];
        soff = o;
    }
    __syncthreads();
    int i = blockIdx.x * 256 + threadIdx.x;
    if (i == 0) { d_rowptr[0] = 0; d_cursor[0] = 0; }
    if (i < NN) {
        int v = d_rowptr[i + 1] + soff;
        d_rowptr[i + 1] = v;
        if (i + 1 < NN) d_cursor[i + 1] = v;
    }
}

// ---------------- fused fill: csr_fill + xprep + bprep ----------------
// B reorder: cg in [0,512): nb=cg>>7, c=cg&127: wn=(c>>6), g=(c>>4)&3, jh=(c>>3)&1, s=c&7
// jg = nb*32 + wn*16 + jh*8 + s ; G = g*128 + jg
__global__ void fused_fill_kernel(const int* __restrict__ ei,
                                  const float* __restrict__ x_seq,
                                  const float* __restrict__ Wih,
                                  const float* __restrict__ Whh) {
    int b = blockIdx.x;
    if (b < 6250) {
        int e = b * 256 + threadIdx.x;
        int s = ei[e];
        int d = ei[EE + e];
        int idx = atomicAdd(&d_cursor[d], 1);
        d_csr[idx] = s;
    } else if (b < 25000) {
        int id = (b - 6250) * 256 + threadIdx.x;
        if (id >= NN * 96) return;
        int n = id / 96, r = id % 96;
        int t = r >> 2, c4 = r & 3;
        float dn = d_dinv[n];
        float4 v = *(const float4*)(x_seq + ((size_t)t * NN + n) * F + c4 * 4);
        __half h[4] = {__float2half_rn(v.x * dn), __float2half_rn(v.y * dn),
                       __float2half_rn(v.z * dn), __float2half_rn(v.w * dn)};
        *(uint2*)(d_xh + (size_t)n * 384 + r * 4) = *(uint2*)h;
    } else {
        int id = (b - 25000) * 256 + threadIdx.x;
        if (id >= 512 * 24) return;
        int cg = id / 24, u = id % 24;
        int nb = cg >> 7, c = cg & 127;
        int wn = c >> 6, g = (c >> 4) & 3, jh = (c >> 3) & 1, s = c & 7;
        int jg = nb * 32 + wn * 16 + jh * 8 + s;
        int G = g * 128 + jg;
        union { __half h[8]; uint4 q; } up;
        #pragma unroll
        for (int e = 0; e < 8; e++) {
            int k = u * 8 + e;
            float v = (k < 64) ? Wih[G * 64 + k] : Whh[G * 128 + (k - 64)];
            up.h[e] = __float2half_rn(v);
        }
        d_Bp[(size_t)cg * 24 + u] = up.q;
    }
}

// ---------------- fused agg1 + mm1 (8-t chunks, dinv folded, MLP8) ----------------
__global__ void __launch_bounds__(256) agg1mm1_kernel(const float* __restrict__ W1,
                                                      const float* __restrict__ b1) {
    __shared__ float W1s[F * H];
    __shared__ float b1s[H];
    __shared__ float ys[8][128];
    int tid = threadIdx.x, w = tid >> 5, lane = tid & 31;
    for (int i = tid; i < F * H; i += 256) W1s[i] = W1[i];
    if (tid < H) b1s[tid] = b1[tid];
    int n = blockIdx.x * 8 + w;
    int q = blockIdx.y;
    float dn = d_dinv[n];
    const uint2* xr = (const uint2*)d_xh;
    uint2 u = xr[(size_t)n * 96 + q * 32 + lane];
    float2 p0 = __half22float2(*(__half2*)&u.x);
    float2 p1 = __half22float2(*(__half2*)&u.y);
    float a0 = p0.x, a1 = p0.y, a2 = p1.x, a3 = p1.y;
    int e = d_rowptr[n], e1 = d_rowptr[n + 1];
    for (; e + 8 <= e1; e += 8) {
        int si[8];
        #pragma unroll
        for (int k = 0; k < 8; k++) si[k] = d_csr[e + k];
        #pragma unroll
        for (int k = 0; k < 8; k++) {
            uint2 v = xr[(size_t)si[k] * 96 + q * 32 + lane];
            float2 q0 = __half22float2(*(__half2*)&v.x);
            float2 q1 = __half22float2(*(__half2*)&v.y);
            a0 += q0.x; a1 += q0.y; a2 += q1.x; a3 += q1.y;
        }
    }
    for (; e < e1; e++) {
        int s = d_csr[e];
        uint2 v = xr[(size_t)s * 96 + q * 32 + lane];
        float2 q0 = __half22float2(*(__half2*)&v.x);
        float2 q1 = __half22float2(*(__half2*)&v.y);
        a0 += q0.x; a1 += q0.y; a2 += q1.x; a3 += q1.y;
    }
    ys[w][lane * 4 + 0] = a0 * dn; ys[w][lane * 4 + 1] = a1 * dn;
    ys[w][lane * 4 + 2] = a2 * dn; ys[w][lane * 4 + 3] = a3 * dn;
    __syncthreads();
    int n2 = tid >> 5, t2 = lane >> 2, jq = lane & 3;
    int ng = blockIdx.x * 8 + n2;
    float dscale = d_dinv[ng];
    float yv[16];
    #pragma unroll
    for (int k = 0; k < 16; k++) yv[k] = ys[n2][t2 * 16 + k];
    float o[16];
    #pragma unroll
    for (int jj = 0; jj < 16; jj++) o[jj] = b1s[jq * 16 + jj];
    #pragma unroll
    for (int k = 0; k < 16; k++)
        #pragma unroll
        for (int jj = 0; jj < 16; jj++)
            o[jj] = fmaf(yv[k], W1s[k * 64 + jq * 16 + jj], o[jj]);
    __half hp[16];
    #pragma unroll
    for (int jj = 0; jj < 16; jj++)
        hp[jj] = __float2half_rn(fmaxf(o[jj], 0.0f) * dscale);
    int tg = q * 8 + t2;
    __half* dst = d_h1 + ((size_t)tg * NN + ng) * 64 + jq * 16;
    *(uint4*)dst = *(uint4*)hp;
    *(uint4*)(dst + 8) = *(uint4*)(hp + 8);
}

// ---------------- fused agg2 + mm2 (4-t chunks, dinv folded, MLP8) ----------------
__global__ void __launch_bounds__(256) agg2mm2_kernel(const float* __restrict__ W2,
                                                      const float* __restrict__ b2) {
    __shared__ float W2s[H * H];
    __shared__ float b2s[H];
    __shared__ float zs[8][4][64];
    int tid = threadIdx.x, w = tid >> 5, lane = tid & 31;
    for (int i = tid; i < H * H; i += 256) W2s[i] = W2[i];
    if (tid < H) b2s[tid] = b2[tid];
    int n = blockIdx.x * 8 + w;
    int q = blockIdx.y;
    float dn = d_dinv[n];
    const uint* h1u = (const uint*)d_h1;
    float acc[4][2];
    #pragma unroll
    for (int tt = 0; tt < 4; tt++) {
        uint u = h1u[((size_t)(q * 4 + tt) * NN + n) * 32 + lane];
        float2 p = __half22float2(*(__half2*)&u);
        acc[tt][0] = p.x; acc[tt][1] = p.y;
    }
    int e = d_rowptr[n], e1 = d_rowptr[n + 1];
    for (; e + 8 <= e1; e += 8) {
        int si[8];
        #pragma unroll
        for (int u2 = 0; u2 < 8; u2++) si[u2] = d_csr[e + u2];
        #pragma unroll
        for (int u2 = 0; u2 < 8; u2++) {
            #pragma unroll
            for (int tt = 0; tt < 4; tt++) {
                uint v = h1u[((size_t)(q * 4 + tt) * NN + si[u2]) * 32 + lane];
                float2 p = __half22float2(*(__half2*)&v);
                acc[tt][0] += p.x; acc[tt][1] += p.y;
            }
        }
    }
    for (; e < e1; e++) {
        int s = d_csr[e];
        #pragma unroll
        for (int tt = 0; tt < 4; tt++) {
            uint v = h1u[((size_t)(q * 4 + tt) * NN + s) * 32 + lane];
            float2 p = __half22float2(*(__half2*)&v);
            acc[tt][0] += p.x; acc[tt][1] += p.y;
        }
    }
    #pragma unroll
    for (int tt = 0; tt < 4; tt++) {
        zs[w][tt][lane * 2] = acc[tt][0] * dn;
        zs[w][tt][lane * 2 + 1] = acc[tt][1] * dn;
    }
    __syncthreads();
    int n2 = tid >> 5, t2 = (lane >> 3) & 3, j0 = (lane & 7) * 8;
    float o[8];
    #pragma unroll
    for (int jj = 0; jj < 8; jj++) o[jj] = b2s[j0 + jj];
    #pragma unroll 8
    for (int k = 0; k < 64; k++) {
        float zv = zs[n2][t2][k];
        float4 w0 = *(float4*)(W2s + k * 64 + j0);
        float4 w1 = *(float4*)(W2s + k * 64 + j0 + 4);
        o[0] = fmaf(zv, w0.x, o[0]); o[1] = fmaf(zv, w0.y, o[1]);
        o[2] = fmaf(zv, w0.z, o[2]); o[3] = fmaf(zv, w0.w, o[3]);
        o[4] = fmaf(zv, w1.x, o[4]); o[5] = fmaf(zv, w1.y, o[5]);
        o[6] = fmaf(zv, w1.z, o[6]); o[7] = fmaf(zv, w1.w, o[7]);
    }
    __half hp[8];
    #pragma unroll
    for (int jj = 0; jj < 8; jj++)
        hp[jj] = __float2half_rn(fmaxf(o[jj], 0.0f));
    int ng = blockIdx.x * 8 + n2;
    size_t base = ((size_t)(q * 4 + t2) * NPAD + ng) * 64 + j0;
    *(uint4*)(d_h2 + base) = *(uint4*)hp;
}

// ---------------- A staging: single fp16 plane, cp.async ----------------
__device__ __forceinline__ void stageA(
    char* smem, uint32_t sb, int buf, int tile, bool zero_h,
    const __half* h2, const __half* hp, int tid) {
    int row0 = tile * 128;
    uint32_t bufb = sb + AOFF + buf * 51200;
    #pragma unroll
    for (int it = 0; it < 12; it++) {
        int i = tid + it * 256;                  // 0..3071
        int row = i / 24, u = i % 24;
        uint32_t dst = bufb + row * 400 + u * 16;
        if (u < 8) {
            cp16(dst, h2 + (size_t)(row0 + row) * 64 + u * 8);
        } else if (!zero_h) {
            cp16(dst, hp + (size_t)(row0 + row) * 128 + (u - 8) * 8);
        } else {
            *(uint4*)(smem + AOFF + buf * 51200 + row * 400 + u * 16) =
                make_uint4(0, 0, 0, 0);
        }
    }
    asm volatile("cp.async.commit_group;" ::: "memory");
}

// ---------------- persistent LSTM: single-pass fp16, M=128 tiles ----------------
__global__ void __launch_bounds__(256, 1) lstm_persist(const float* __restrict__ bih,
                                                       const float* __restrict__ bhh) {
    extern __shared__ char smem[];
    float* bs = (float*)smem;
    uint32_t sb = smem_u32(smem);
    const int tid = threadIdx.x, lane = tid & 31, wid = tid >> 5;
    const int nb = blockIdx.x & 3;
    const int gidx = blockIdx.x >> 2;          // 0..36
    const int cnt = (gidx < NTILES128 - NGRP * 10) ? 11 : 10;   // 391 = 21*11 + 16*10

    for (int j = tid; j < 512; j += 256) bs[j] = bih[j] + bhh[j];
    for (int i = tid; i < 128 * 24; i += 256) {
        int col = i / 24, u = i % 24;
        uint4 v = d_Bp[(size_t)(nb * 128 + col) * 24 + u];
        *(uint4*)(smem + BOFF + col * 400 + u * 16) = v;
    }
    __syncthreads();

    const int wm = wid & 3;                    // row quarter (32 rows)
    const int wn = wid >> 2;                   // col half (64 cols)
    const int q = lane >> 3, r8 = lane & 7;
    const uint32_t aRowOff = (uint32_t)((wm * 32 + (q & 1) * 8 + r8) * 400 + ((q >> 1) * 8) * 2);
    const uint32_t bRowBase = (uint32_t)((wn * 64 + (q >> 1) * 8 + r8) * 400 + (q & 1) * 16);
    const int gq = lane >> 2, tq = lane & 3;

    for (int t = 0; t < T_STEPS; t++) {
        const __half* h2 = d_h2 + (size_t)t * NPAD * 64;
        const __half* hp = (t & 1) ? d_hs1 : d_hs0;
        __half* hn = (t & 1) ? d_hs0 : d_hs1;
        const bool z = (t == 0);

        stageA(smem, sb, 0, gidx, z, h2, hp, tid);

        for (int k = 0; k < cnt; k++) {
            int tile = gidx + k * NGRP;
            if (k + 1 < cnt) {
                stageA(smem, sb, (k + 1) & 1, gidx + (k + 1) * NGRP, z, h2, hp, tid);
                asm volatile("cp.async.wait_group 1;" ::: "memory");
            } else {
                asm volatile("cp.async.wait_group 0;" ::: "memory");
            }
            __syncthreads();

            float acc[2][8][4];
            #pragma unroll
            for (int mi = 0; mi < 2; mi++)
                #pragma unroll
                for (int nt = 0; nt < 8; nt++)
                    #pragma unroll
                    for (int r = 0; r < 4; r++) acc[mi][nt][r] = 0.0f;

            uint32_t aB = sb + AOFF + (k & 1) * 51200 + aRowOff;
            uint32_t bB = sb + BOFF + bRowBase;
            #pragma unroll 1
            for (int ks = 0; ks < 12; ks++) {
                uint32_t a[2][4];
                ldsm4(a[0], aB + ks * 32);
                ldsm4(a[1], aB + 16 * 400 + ks * 32);
                uint32_t b[8][2];
                #pragma unroll
                for (int pr = 0; pr < 4; pr++) {
                    uint32_t t4[4];
                    ldsm4(t4, bB + pr * (16 * 400) + ks * 32);
                    b[2 * pr][0] = t4[0]; b[2 * pr][1] = t4[1];
                    b[2 * pr + 1][0] = t4[2]; b[2 * pr + 1][1] = t4[3];
                }
                #pragma unroll
                for (int mi = 0; mi < 2; mi++)
                    #pragma unroll
                    for (int nt = 0; nt < 8; nt++)
                        mma16816(acc[mi][nt], a[mi], b[nt]);
            }

            // fused LSTM epilogue
            int row0 = tile * 128;
            #pragma unroll
            for (int mi = 0; mi < 2; mi++) {
                #pragma unroll
                for (int h = 0; h < 2; h++) {
                    int rl = wm * 32 + mi * 16 + h * 8 + gq;
                    int n = row0 + rl;
                    #pragma unroll
                    for (int jh = 0; jh < 2; jh++) {
                        int jl0 = wn * 16 + jh * 8 + 2 * tq;
                        float* cptr = d_cs2 + ((size_t)nb * NPAD + n) * 32 + jl0;
                        float2 cp = z ? make_float2(0.0f, 0.0f) : *(float2*)cptr;
                        __half hout[2];
                        #pragma unroll
                        for (int p = 0; p < 2; p++) {
                            int jgl = nb * 32 + jl0 + p;
                            int ci = h * 2 + p;
                            float gi = acc[mi][0 + jh][ci] + bs[jgl];
                            float gf = acc[mi][2 + jh][ci] + bs[128 + jgl];
                            float gG = acc[mi][4 + jh][ci] + bs[256 + jgl];
                            float go = acc[mi][6 + jh][ci] + bs[384 + jgl];
                            float cold = p ? cp.y : cp.x;
                            float cn = sigt(gf) * cold + sigt(gi) * tanha(gG);
                            float hv = sigt(go) * tanha(cn);
                            if (p) cp.y = cn; else cp.x = cn;
                            hout[p] = __float2half_rn(hv);
                        }
                        *(float2*)cptr = cp;
                        *(uint*)(hn + (size_t)n * 128 + nb * 32 + jl0) = *(uint*)hout;
                    }
                }
            }
            __syncthreads();
        }

        if (t < T_STEPS - 1) {
            __syncthreads();
            if (tid == 0) {
                __threadfence();
                atomicAdd(&d_bar, 1u);
                unsigned target = (unsigned)NCTAS * (unsigned)(t + 1);
                unsigned v;
                do {
                    asm volatile("ld.acquire.gpu.global.u32 %0, [%1];"
                                 : "=r"(v) : "l"(&d_bar) : "memory");
                    if (v < target) asm volatile("nanosleep.u32 64;");
                } while (v < target);
            }
            __syncthreads();
        }
    }
}

// ---------------- FC head ----------------
__global__ void fc_kernel(const __half* __restrict__ hfin,
                          const float* __restrict__ Wf1, const float* __restrict__ bf1,
                          const float* __restrict__ Wf2, const float* __restrict__ bf2,
                          float* __restrict__ out) {
    __shared__ float Ws[LH * 32];
    __shared__ float hsm[32][LH];
    int tid = threadIdx.x;
    for (int i = tid; i < LH * 32; i += 256) Ws[i] = Wf1[i];
    int n0 = blockIdx.x * 32;
    for (int i = tid; i < 32 * LH; i += 256) {
        int nl = i >> 7, k = i & 127;
        int n = n0 + nl;
        hsm[nl][k] = (n < NN) ? __half2float(hfin[(size_t)n * 128 + k]) : 0.0f;
    }
    __syncthreads();
    int w = tid >> 5, lane = tid & 31;
    float wf2 = Wf2[lane];
    float bb1 = bf1[lane];
    for (int r = 0; r < 4; r++) {
        int nl = w * 4 + r;
        int n = n0 + nl;
        float acc = bb1;
        #pragma unroll
        for (int k = 0; k < LH; k++) acc = fmaf(hsm[nl][k], Ws[k * 32 + lane], acc);
        acc = fmaxf(acc, 0.0f) * wf2;
        #pragma unroll
        for (int off = 16; off > 0; off >>= 1)
            acc += __shfl_down_sync(0xffffffffu, acc, off);
        if (lane == 0 && n < NN) out[n] = acc + bf2[0];
    }
}

// ---------------- launcher ----------------
extern "C" void kernel_launch(void* const* d_in, const int* in_sizes, int n_in,
                              void* d_out, int out_size) {
    const float* x_seq = (const float*)d_in[0];
    const int*   ei    = (const int*)d_in[1];
    const float* W1    = (const float*)d_in[2];
    const float* b1    = (const float*)d_in[3];
    const float* W2    = (const float*)d_in[4];
    const float* b2    = (const float*)d_in[5];
    const float* Wih   = (const float*)d_in[6];
    const float* Whh   = (const float*)d_in[7];
    const float* bih   = (const float*)d_in[8];
    const float* bhh   = (const float*)d_in[9];
    const float* Wf1   = (const float*)d_in[10];
    const float* bf1   = (const float*)d_in[11];
    const float* Wf2   = (const float*)d_in[12];
    const float* bf2   = (const float*)d_in[13];
    float* out = (float*)d_out;

    cudaFuncSetAttribute(lstm_persist, cudaFuncAttributeMaxDynamicSharedMemorySize,
                         PERSIST_SMEM);

    void* degp;
    cudaGetSymbolAddress(&degp, d_deg);
    cudaMemsetAsync(degp, 0, NN * sizeof(int));

    __half* hs0;
    cudaGetSymbolAddress((void**)&hs0, d_hs0);

    deg_kernel<<<(EE + 255) / 256, 256>>>(ei);
    dinv_scan_kernel<<<SCAN_NB, 512>>>();
    scan_add2_kernel<<<(NN + 255) / 256, 256>>>();
    fused_fill_kernel<<<25048, 256>>>(ei, x_seq, Wih, Whh);
    agg1mm1_kernel<<<dim3(NN / 8, 3), 256>>>(W1, b1);
    agg2mm2_kernel<<<dim3(NN / 8, 6), 256>>>(W2, b2);
    lstm_persist<<<NCTAS, 256, PERSIST_SMEM>>>(bih, bhh);
    fc_kernel<<<(NN + 31) / 32, 256>>>(hs0, Wf1, bf1, Wf2, bf2, out);
}

// round 10
// speedup vs baseline: 2.3047x; 1.0261x over previous
#include <cuda_runtime.h>
#include <cuda_bf16.h>
#include <cuda_fp16.h>
#include <math.h>
#include <stdint.h>

#define T_STEPS 24
#define NN 50000
#define NPAD 50048
#define EE 1600000
#define F 16
#define H 64
#define LH 128
#define SCAN_NB 98

#define NTILES128 391           // NPAD/128
#define NCTAS 148
#define NGRP 37                 // CTA groups per nb (148/4)

// persistent-kernel smem layout (single-plane B)
#define BIAS_OFF 0              // 512 floats = 2048 B
#define BOFF 2048               // B fp16: 128 * 400 = 51200
#define AOFF (2048 + 51200)     // A double buffer: 2 * 51200 (128 rows x 400 B)
#define PERSIST_SMEM (AOFF + 2 * 51200)   // 155648

// ---------------- helpers ----------------
__device__ __forceinline__ uint32_t smem_u32(const void* p) {
    uint32_t a;
    asm("{ .reg .u64 t; cvta.to.shared.u64 t, %1; cvt.u32.u64 %0, t; }" : "=r"(a) : "l"(p));
    return a;
}
__device__ __forceinline__ void ldsm4(uint32_t* r, uint32_t addr) {
    asm volatile("ldmatrix.sync.aligned.m8n8.x4.shared.b16 {%0,%1,%2,%3}, [%4];"
                 : "=r"(r[0]), "=r"(r[1]), "=r"(r[2]), "=r"(r[3]) : "r"(addr));
}
__device__ __forceinline__ void mma16816(float* c, const uint32_t* a, const uint32_t* b) {
    asm volatile(
        "mma.sync.aligned.m16n8k16.row.col.f32.f16.f16.f32 "
        "{%0,%1,%2,%3}, {%4,%5,%6,%7}, {%8,%9}, {%0,%1,%2,%3};"
        : "+f"(c[0]), "+f"(c[1]), "+f"(c[2]), "+f"(c[3])
        : "r"(a[0]), "r"(a[1]), "r"(a[2]), "r"(a[3]), "r"(b[0]), "r"(b[1]));
}
__device__ __forceinline__ void cp16(uint32_t dst, const void* src) {
    asm volatile("cp.async.cg.shared.global [%0], [%1], 16;" :: "r"(dst), "l"(src));
}
__device__ __forceinline__ float tanha(float x) {
    float r;
    asm("tanh.approx.f32 %0, %1;" : "=f"(r) : "f"(x));
    return r;
}
__device__ __forceinline__ float sigt(float x) {
    return fmaf(tanha(0.5f * x), 0.5f, 0.5f);
}
__device__ __forceinline__ void acc8(float* a, uint4 v) {
    __half2* h = (__half2*)&v;
    #pragma unroll
    for (int i = 0; i < 4; i++) {
        float2 p = __half22float2(h[i]);
        a[2 * i] += p.x; a[2 * i + 1] += p.y;
    }
}

// ---------------- scratch ----------------
__device__ int   d_deg[NN];
__device__ int   d_rowptr[NN + 1];
__device__ int   d_cursor[NN];
__device__ int   d_csr[EE];
__device__ int   d_blocksum[128];
__device__ float d_dinv[NN];
__device__ unsigned d_bar;
__device__ __half d_xh[19200000];                 // [n][t*16+c]  (x * dinv[n])
__device__ __half d_h1[76800000];                 // [q][n][4t][64]   (h1 * dinv[n])
__device__ __half d_h2[76873728];                 // [t][NPAD][64] fp16
__device__ __half d_hs0[6406144];                 // [NPAD][128] fp16 h
__device__ __half d_hs1[6406144];
__device__ float d_cs2[6406144];                  // [nb][NPAD][32]
__device__ uint4 d_Bp[512 * 24];                  // fp16 weights, reordered cols

// ---------------- CSR build ----------------
__global__ void deg_kernel(const int* __restrict__ ei) {
    int e = blockIdx.x * 256 + threadIdx.x;
    if (e < EE) atomicAdd(&d_deg[ei[EE + e]], 1);
}
__global__ void dinv_scan_kernel() {
    __shared__ int s[512];
    int tid = threadIdx.x;
    int i = blockIdx.x * 512 + tid;
    if (i == 0) d_bar = 0;
    int v = (i < NN) ? d_deg[i] : 0;
    if (i < NN) d_dinv[i] = rsqrtf((float)v + 1.0f);
    s[tid] = v;
    __syncthreads();
    #pragma unroll
    for (int off = 1; off < 512; off <<= 1) {
        int t = (tid >= off) ? s[tid - off] : 0;
        __syncthreads();
        s[tid] += t;
        __syncthreads();
    }
    if (i < NN) d_rowptr[i + 1] = s[tid];
    if (tid == 511) d_blocksum[blockIdx.x] = s[511];
}
__global__ void scan_add2_kernel() {
    __shared__ int soff;
    int sbk = blockIdx.x >> 1;
    if (threadIdx.x == 0) {
        int o = 0;
        for (int j = 0; j < sbk; j++) o += d_blocksum[j];
        soff = o;
    }
    __syncthreads();
    int i = blockIdx.x * 256 + threadIdx.x;
    if (i == 0) { d_rowptr[0] = 0; d_cursor[0] = 0; }
    if (i < NN) {
        int v = d_rowptr[i + 1] + soff;
        d_rowptr[i + 1] = v;
        if (i + 1 < NN) d_cursor[i + 1] = v;
    }
}

// ---------------- fused fill: csr_fill + xprep + bprep ----------------
__global__ void fused_fill_kernel(const int* __restrict__ ei,
                                  const float* __restrict__ x_seq,
                                  const float* __restrict__ Wih,
                                  const float* __restrict__ Whh) {
    int b = blockIdx.x;
    if (b < 6250) {
        int e = b * 256 + threadIdx.x;
        int s = ei[e];
        int d = ei[EE + e];
        int idx = atomicAdd(&d_cursor[d], 1);
        d_csr[idx] = s;
    } else if (b < 25000) {
        int id = (b - 6250) * 256 + threadIdx.x;
        if (id >= NN * 96) return;
        int n = id / 96, r = id % 96;
        int t = r >> 2, c4 = r & 3;
        float dn = d_dinv[n];
        float4 v = *(const float4*)(x_seq + ((size_t)t * NN + n) * F + c4 * 4);
        __half h[4] = {__float2half_rn(v.x * dn), __float2half_rn(v.y * dn),
                       __float2half_rn(v.z * dn), __float2half_rn(v.w * dn)};
        *(uint2*)(d_xh + (size_t)n * 384 + r * 4) = *(uint2*)h;
    } else {
        int id = (b - 25000) * 256 + threadIdx.x;
        if (id >= 512 * 24) return;
        int cg = id / 24, u = id % 24;
        int nb = cg >> 7, c = cg & 127;
        int wn = c >> 6, g = (c >> 4) & 3, jh = (c >> 3) & 1, s = c & 7;
        int jg = nb * 32 + wn * 16 + jh * 8 + s;
        int G = g * 128 + jg;
        union { __half h[8]; uint4 q; } up;
        #pragma unroll
        for (int e = 0; e < 8; e++) {
            int k = u * 8 + e;
            float v = (k < 64) ? Wih[G * 64 + k] : Whh[G * 128 + (k - 64)];
            up.h[e] = __float2half_rn(v);
        }
        d_Bp[(size_t)cg * 24 + u] = up.q;
    }
}

// ---------------- fused agg1 + mm1 (8-t chunks, dinv folded, MLP8) ----------------
__global__ void __launch_bounds__(256) agg1mm1_kernel(const float* __restrict__ W1,
                                                      const float* __restrict__ b1) {
    __shared__ float W1s[F * H];
    __shared__ float b1s[H];
    __shared__ float ys[8][128];
    int tid = threadIdx.x, w = tid >> 5, lane = tid & 31;
    for (int i = tid; i < F * H; i += 256) W1s[i] = W1[i];
    if (tid < H) b1s[tid] = b1[tid];
    int n = blockIdx.x * 8 + w;
    int q = blockIdx.y;
    float dn = d_dinv[n];
    const uint2* xr = (const uint2*)d_xh;
    uint2 u = xr[(size_t)n * 96 + q * 32 + lane];
    float2 p0 = __half22float2(*(__half2*)&u.x);
    float2 p1 = __half22float2(*(__half2*)&u.y);
    float a0 = p0.x, a1 = p0.y, a2 = p1.x, a3 = p1.y;
    int e = d_rowptr[n], e1 = d_rowptr[n + 1];
    for (; e + 8 <= e1; e += 8) {
        int si[8];
        #pragma unroll
        for (int k = 0; k < 8; k++) si[k] = d_csr[e + k];
        #pragma unroll
        for (int k = 0; k < 8; k++) {
            uint2 v = xr[(size_t)si[k] * 96 + q * 32 + lane];
            float2 q0 = __half22float2(*(__half2*)&v.x);
            float2 q1 = __half22float2(*(__half2*)&v.y);
            a0 += q0.x; a1 += q0.y; a2 += q1.x; a3 += q1.y;
        }
    }
    for (; e < e1; e++) {
        int s = d_csr[e];
        uint2 v = xr[(size_t)s * 96 + q * 32 + lane];
        float2 q0 = __half22float2(*(__half2*)&v.x);
        float2 q1 = __half22float2(*(__half2*)&v.y);
        a0 += q0.x; a1 += q0.y; a2 += q1.x; a3 += q1.y;
    }
    ys[w][lane * 4 + 0] = a0 * dn; ys[w][lane * 4 + 1] = a1 * dn;
    ys[w][lane * 4 + 2] = a2 * dn; ys[w][lane * 4 + 3] = a3 * dn;
    __syncthreads();
    int n2 = tid >> 5, t2 = lane >> 2, jq = lane & 3;
    int ng = blockIdx.x * 8 + n2;
    float dscale = d_dinv[ng];
    float yv[16];
    #pragma unroll
    for (int k = 0; k < 16; k++) yv[k] = ys[n2][t2 * 16 + k];
    float o[16];
    #pragma unroll
    for (int jj = 0; jj < 16; jj++) o[jj] = b1s[jq * 16 + jj];
    #pragma unroll
    for (int k = 0; k < 16; k++)
        #pragma unroll
        for (int jj = 0; jj < 16; jj++)
            o[jj] = fmaf(yv[k], W1s[k * 64 + jq * 16 + jj], o[jj]);
    __half hp[16];
    #pragma unroll
    for (int jj = 0; jj < 16; jj++)
        hp[jj] = __float2half_rn(fmaxf(o[jj], 0.0f) * dscale);
    // h1 layout [qq][n][tt][64], qq = t/4, tt = t%4
    int t = q * 8 + t2;
    int qq = t >> 2, tt = t & 3;
    __half* dst = d_h1 + (((size_t)qq * NN + ng) * 4 + tt) * 64 + jq * 16;
    *(uint4*)dst = *(uint4*)hp;
    *(uint4*)(dst + 8) = *(uint4*)(hp + 8);
}

// ---------------- fused agg2 + mm2 (4-t chunks, single LDG.128 per edge) ----------------
__global__ void __launch_bounds__(256) agg2mm2_kernel(const float* __restrict__ W2,
                                                      const float* __restrict__ b2) {
    __shared__ float W2s[H * H];
    __shared__ float b2s[H];
    __shared__ float zs[8][4][66];
    int tid = threadIdx.x, w = tid >> 5, lane = tid & 31;
    for (int i = tid; i < H * H; i += 256) W2s[i] = W2[i];
    if (tid < H) b2s[tid] = b2[tid];
    int n = blockIdx.x * 8 + w;
    int q = blockIdx.y;
    float dn = d_dinv[n];
    // h1 as uint4: per (q,n) = 32 uint4 (4t x 64 halfs). lane -> tt=lane>>3, cols (lane&7)*8..
    const uint4* h1q = (const uint4*)d_h1 + (size_t)q * NN * 32;
    float acc[8];
    {
        uint4 sv = h1q[(size_t)n * 32 + lane];
        __half2* h = (__half2*)&sv;
        #pragma unroll
        for (int i = 0; i < 4; i++) {
            float2 p = __half22float2(h[i]);
            acc[2 * i] = p.x; acc[2 * i + 1] = p.y;
        }
    }
    int e = d_rowptr[n], e1 = d_rowptr[n + 1];
    for (; e + 8 <= e1; e += 8) {
        int si[8];
        #pragma unroll
        for (int u2 = 0; u2 < 8; u2++) si[u2] = d_csr[e + u2];
        uint4 v[8];
        #pragma unroll
        for (int u2 = 0; u2 < 8; u2++) v[u2] = h1q[(size_t)si[u2] * 32 + lane];
        #pragma unroll
        for (int u2 = 0; u2 < 8; u2++) acc8(acc, v[u2]);
    }
    for (; e < e1; e++) {
        int s = d_csr[e];
        acc8(acc, h1q[(size_t)s * 32 + lane]);
    }
    {
        int tt = lane >> 3, cb = (lane & 7) * 8;
        #pragma unroll
        for (int i = 0; i < 8; i++) zs[w][tt][cb + i] = acc[i] * dn;
    }
    __syncthreads();
    int n2 = tid >> 5, t2 = (lane >> 3) & 3, j0 = (lane & 7) * 8;
    float o[8];
    #pragma unroll
    for (int jj = 0; jj < 8; jj++) o[jj] = b2s[j0 + jj];
    #pragma unroll 8
    for (int k = 0; k < 64; k++) {
        float zv = zs[n2][t2][k];
        float4 w0 = *(float4*)(W2s + k * 64 + j0);
        float4 w1 = *(float4*)(W2s + k * 64 + j0 + 4);
        o[0] = fmaf(zv, w0.x, o[0]); o[1] = fmaf(zv, w0.y, o[1]);
        o[2] = fmaf(zv, w0.z, o[2]); o[3] = fmaf(zv, w0.w, o[3]);
        o[4] = fmaf(zv, w1.x, o[4]); o[5] = fmaf(zv, w1.y, o[5]);
        o[6] = fmaf(zv, w1.z, o[6]); o[7] = fmaf(zv, w1.w, o[7]);
    }
    __half hp[8];
    #pragma unroll
    for (int jj = 0; jj < 8; jj++)
        hp[jj] = __float2half_rn(fmaxf(o[jj], 0.0f));
    int ng = blockIdx.x * 8 + n2;
    size_t base = ((size_t)(q * 4 + t2) * NPAD + ng) * 64 + j0;
    *(uint4*)(d_h2 + base) = *(uint4*)hp;
}

// ---------------- A staging: single fp16 plane, cp.async ----------------
__device__ __forceinline__ void stageA(
    char* smem, uint32_t sb, int buf, int tile, bool zero_h,
    const __half* h2, const __half* hp, int tid) {
    int row0 = tile * 128;
    uint32_t bufb = sb + AOFF + buf * 51200;
    #pragma unroll
    for (int it = 0; it < 12; it++) {
        int i = tid + it * 256;                  // 0..3071
        int row = i / 24, u = i % 24;
        uint32_t dst = bufb + row * 400 + u * 16;
        if (u < 8) {
            cp16(dst, h2 + (size_t)(row0 + row) * 64 + u * 8);
        } else if (!zero_h) {
            cp16(dst, hp + (size_t)(row0 + row) * 128 + (u - 8) * 8);
        } else {
            *(uint4*)(smem + AOFF + buf * 51200 + row * 400 + u * 16) =
                make_uint4(0, 0, 0, 0);
        }
    }
    asm volatile("cp.async.commit_group;" ::: "memory");
}

// ---------------- persistent LSTM: single-pass fp16, M=128 tiles ----------------
__global__ void __launch_bounds__(256, 1) lstm_persist(const float* __restrict__ bih,
                                                       const float* __restrict__ bhh) {
    extern __shared__ char smem[];
    float* bs = (float*)smem;
    uint32_t sb = smem_u32(smem);
    const int tid = threadIdx.x, lane = tid & 31, wid = tid >> 5;
    const int nb = blockIdx.x & 3;
    const int gidx = blockIdx.x >> 2;          // 0..36
    const int cnt = (gidx < NTILES128 - NGRP * 10) ? 11 : 10;   // 391 = 21*11 + 16*10

    for (int j = tid; j < 512; j += 256) bs[j] = bih[j] + bhh[j];
    for (int i = tid; i < 128 * 24; i += 256) {
        int col = i / 24, u = i % 24;
        uint4 v = d_Bp[(size_t)(nb * 128 + col) * 24 + u];
        *(uint4*)(smem + BOFF + col * 400 + u * 16) = v;
    }
    __syncthreads();

    const int wm = wid & 3;                    // row quarter (32 rows)
    const int wn = wid >> 2;                   // col half (64 cols)
    const int q = lane >> 3, r8 = lane & 7;
    const uint32_t aRowOff = (uint32_t)((wm * 32 + (q & 1) * 8 + r8) * 400 + ((q >> 1) * 8) * 2);
    const uint32_t bRowBase = (uint32_t)((wn * 64 + (q >> 1) * 8 + r8) * 400 + (q & 1) * 16);
    const int gq = lane >> 2, tq = lane & 3;

    for (int t = 0; t < T_STEPS; t++) {
        const __half* h2 = d_h2 + (size_t)t * NPAD * 64;
        const __half* hp = (t & 1) ? d_hs1 : d_hs0;
        __half* hn = (t & 1) ? d_hs0 : d_hs1;
        const bool z = (t == 0);

        stageA(smem, sb, 0, gidx, z, h2, hp, tid);

        for (int k = 0; k < cnt; k++) {
            int tile = gidx + k * NGRP;
            if (k + 1 < cnt) {
                stageA(smem, sb, (k + 1) & 1, gidx + (k + 1) * NGRP, z, h2, hp, tid);
                asm volatile("cp.async.wait_group 1;" ::: "memory");
            } else {
                asm volatile("cp.async.wait_group 0;" ::: "memory");
            }
            __syncthreads();

            float acc[2][8][4];
            #pragma unroll
            for (int mi = 0; mi < 2; mi++)
                #pragma unroll
                for (int nt = 0; nt < 8; nt++)
                    #pragma unroll
                    for (int r = 0; r < 4; r++) acc[mi][nt][r] = 0.0f;

            uint32_t aB = sb + AOFF + (k & 1) * 51200 + aRowOff;
            uint32_t bB = sb + BOFF + bRowBase;
            #pragma unroll 1
            for (int ks = 0; ks < 12; ks++) {
                uint32_t a[2][4];
                ldsm4(a[0], aB + ks * 32);
                ldsm4(a[1], aB + 16 * 400 + ks * 32);
                uint32_t b[8][2];
                #pragma unroll
                for (int pr = 0; pr < 4; pr++) {
                    uint32_t t4[4];
                    ldsm4(t4, bB + pr * (16 * 400) + ks * 32);
                    b[2 * pr][0] = t4[0]; b[2 * pr][1] = t4[1];
                    b[2 * pr + 1][0] = t4[2]; b[2 * pr + 1][1] = t4[3];
                }
                #pragma unroll
                for (int mi = 0; mi < 2; mi++)
                    #pragma unroll
                    for (int nt = 0; nt < 8; nt++)
                        mma16816(acc[mi][nt], a[mi], b[nt]);
            }

            // fused LSTM epilogue
            int row0 = tile * 128;
            #pragma unroll
            for (int mi = 0; mi < 2; mi++) {
                #pragma unroll
                for (int h = 0; h < 2; h++) {
                    int rl = wm * 32 + mi * 16 + h * 8 + gq;
                    int n = row0 + rl;
                    #pragma unroll
                    for (int jh = 0; jh < 2; jh++) {
                        int jl0 = wn * 16 + jh * 8 + 2 * tq;
                        float* cptr = d_cs2 + ((size_t)nb * NPAD + n) * 32 + jl0;
                        float2 cp = z ? make_float2(0.0f, 0.0f) : *(float2*)cptr;
                        __half hout[2];
                        #pragma unroll
                        for (int p = 0; p < 2; p++) {
                            int jgl = nb * 32 + jl0 + p;
                            int ci = h * 2 + p;
                            float gi = acc[mi][0 + jh][ci] + bs[jgl];
                            float gf = acc[mi][2 + jh][ci] + bs[128 + jgl];
                            float gG = acc[mi][4 + jh][ci] + bs[256 + jgl];
                            float go = acc[mi][6 + jh][ci] + bs[384 + jgl];
                            float cold = p ? cp.y : cp.x;
                            float cn = sigt(gf) * cold + sigt(gi) * tanha(gG);
                            float hv = sigt(go) * tanha(cn);
                            if (p) cp.y = cn; else cp.x = cn;
                            hout[p] = __float2half_rn(hv);
                        }
                        *(float2*)cptr = cp;
                        *(uint*)(hn + (size_t)n * 128 + nb * 32 + jl0) = *(uint*)hout;
                    }
                }
            }
            __syncthreads();
        }

        if (t < T_STEPS - 1) {
            __syncthreads();
            if (tid == 0) {
                __threadfence();
                atomicAdd(&d_bar, 1u);
                unsigned target = (unsigned)NCTAS * (unsigned)(t + 1);
                unsigned v;
                do {
                    asm volatile("ld.acquire.gpu.global.u32 %0, [%1];"
                                 : "=r"(v) : "l"(&d_bar) : "memory");
                    if (v < target) asm volatile("nanosleep.u32 64;");
                } while (v < target);
            }
            __syncthreads();
        }
    }
}

// ---------------- FC head ----------------
__global__ void fc_kernel(const __half* __restrict__ hfin,
                          const float* __restrict__ Wf1, const float* __restrict__ bf1,
                          const float* __restrict__ Wf2, const float* __restrict__ bf2,
                          float* __restrict__ out) {
    __shared__ float Ws[LH * 32];
    __shared__ float hsm[32][LH];
    int tid = threadIdx.x;
    for (int i = tid; i < LH * 32; i += 256) Ws[i] = Wf1[i];
    int n0 = blockIdx.x * 32;
    for (int i = tid; i < 32 * LH; i += 256) {
        int nl = i >> 7, k = i & 127;
        int n = n0 + nl;
        hsm[nl][k] = (n < NN) ? __half2float(hfin[(size_t)n * 128 + k]) : 0.0f;
    }
    __syncthreads();
    int w = tid >> 5, lane = tid & 31;
    float wf2 = Wf2[lane];
    float bb1 = bf1[lane];
    for (int r = 0; r < 4; r++) {
        int nl = w * 4 + r;
        int n = n0 + nl;
        float acc = bb1;
        #pragma unroll
        for (int k = 0; k < LH; k++) acc = fmaf(hsm[nl][k], Ws[k * 32 + lane], acc);
        acc = fmaxf(acc, 0.0f) * wf2;
        #pragma unroll
        for (int off = 16; off > 0; off >>= 1)
            acc += __shfl_down_sync(0xffffffffu, acc, off);
        if (lane == 0 && n < NN) out[n] = acc + bf2[0];
    }
}

// ---------------- launcher ----------------
extern "C" void kernel_launch(void* const* d_in, const int* in_sizes, int n_in,
                              void* d_out, int out_size) {
    const float* x_seq = (const float*)d_in[0];
    const int*   ei    = (const int*)d_in[1];
    const float* W1    = (const float*)d_in[2];
    const float* b1    = (const float*)d_in[3];
    const float* W2    = (const float*)d_in[4];
    const float* b2    = (const float*)d_in[5];
    const float* Wih   = (const float*)d_in[6];
    const float* Whh   = (const float*)d_in[7];
    const float* bih   = (const float*)d_in[8];
    const float* bhh   = (const float*)d_in[9];
    const float* Wf1   = (const float*)d_in[10];
    const float* bf1   = (const float*)d_in[11];
    const float* Wf2   = (const float*)d_in[12];
    const float* bf2   = (const float*)d_in[13];
    float* out = (float*)d_out;

    cudaFuncSetAttribute(lstm_persist, cudaFuncAttributeMaxDynamicSharedMemorySize,
                         PERSIST_SMEM);

    void* degp;
    cudaGetSymbolAddress(&degp, d_deg);
    cudaMemsetAsync(degp, 0, NN * sizeof(int));

    __half* hs0;
    cudaGetSymbolAddress((void**)&hs0, d_hs0);

    deg_kernel<<<(EE + 255) / 256, 256>>>(ei);
    dinv_scan_kernel<<<SCAN_NB, 512>>>();
    scan_add2_kernel<<<(NN + 255) / 256, 256>>>();
    fused_fill_kernel<<<25048, 256>>>(ei, x_seq, Wih, Whh);
    agg1mm1_kernel<<<dim3(NN / 8, 3), 256>>>(W1, b1);
    agg2mm2_kernel<<<dim3(NN / 8, 6), 256>>>(W2, b2);
    lstm_persist<<<NCTAS, 256, PERSIST_SMEM>>>(bih, bhh);
    fc_kernel<<<(NN + 31) / 32, 256>>>(hs0, Wf1, bf1, Wf2, bf2, out);
}

// round 12
// speedup vs baseline: 2.7364x; 1.1873x over previous
#include <cuda_runtime.h>
#include <cuda_bf16.h>
#include <cuda_fp16.h>
#include <math.h>
#include <stdint.h>

#define T_STEPS 24
#define NN 50000
#define NPAD 50048
#define EE 1600000
#define F 16
#define H 64
#define LH 128
#define SCAN_NB 98

#define MTILE 32
#define NTILES (NPAD / MTILE)     // 1564

// lstm_tile smem: B (512 cols x 400B) + A (32 rows x 400B)
#define BOFF 0
#define AOFF 204800
#define LSTM_SMEM (AOFF + 12800)  // 217600

// ---------------- helpers ----------------
__device__ __forceinline__ uint32_t smem_u32(const void* p) {
    uint32_t a;
    asm("{ .reg .u64 t; cvta.to.shared.u64 t, %1; cvt.u32.u64 %0, t; }" : "=r"(a) : "l"(p));
    return a;
}
__device__ __forceinline__ void ldsm4(uint32_t* r, uint32_t addr) {
    asm volatile("ldmatrix.sync.aligned.m8n8.x4.shared.b16 {%0,%1,%2,%3}, [%4];"
                 : "=r"(r[0]), "=r"(r[1]), "=r"(r[2]), "=r"(r[3]) : "r"(addr));
}
__device__ __forceinline__ void mma16816(float* c, const uint32_t* a, const uint32_t* b) {
    asm volatile(
        "mma.sync.aligned.m16n8k16.row.col.f32.f16.f16.f32 "
        "{%0,%1,%2,%3}, {%4,%5,%6,%7}, {%8,%9}, {%0,%1,%2,%3};"
        : "+f"(c[0]), "+f"(c[1]), "+f"(c[2]), "+f"(c[3])
        : "r"(a[0]), "r"(a[1]), "r"(a[2]), "r"(a[3]), "r"(b[0]), "r"(b[1]));
}
__device__ __forceinline__ void cp16(uint32_t dst, const void* src) {
    asm volatile("cp.async.cg.shared.global [%0], [%1], 16;" :: "r"(dst), "l"(src));
}
__device__ __forceinline__ float tanha(float x) {
    float r;
    asm("tanh.approx.f32 %0, %1;" : "=f"(r) : "f"(x));
    return r;
}
__device__ __forceinline__ float sigt(float x) {
    return fmaf(tanha(0.5f * x), 0.5f, 0.5f);
}
__device__ __forceinline__ void acc8(float* a, uint4 v) {
    __half2* h = (__half2*)&v;
    #pragma unroll
    for (int i = 0; i < 4; i++) {
        float2 p = __half22float2(h[i]);
        a[2 * i] += p.x; a[2 * i + 1] += p.y;
    }
}

// ---------------- scratch ----------------
__device__ int   d_deg[NN];
__device__ int   d_rowptr[NN + 1];
__device__ int   d_cursor[NN];
__device__ int   d_csr[EE];
__device__ int   d_blocksum[128];
__device__ float d_dinv[NN];
__device__ __half d_xh[19200000];                 // [n][t*16+c]  (x * dinv[n])
__device__ __half d_h1[76800000];                 // [q][n][4t][64]   (h1 * dinv[n])
__device__ __half d_h2[76873728];                 // [t][NPAD][64] fp16 (pad rows stay 0)
__device__ uint4 d_Bp[512 * 24];                  // fp16 weights, reordered cols

// ---------------- CSR build ----------------
__global__ void deg_kernel(const int* __restrict__ ei) {
    int e = blockIdx.x * 256 + threadIdx.x;
    if (e < EE) atomicAdd(&d_deg[ei[EE + e]], 1);
}
__global__ void dinv_scan_kernel() {
    __shared__ int s[512];
    int tid = threadIdx.x;
    int i = blockIdx.x * 512 + tid;
    int v = (i < NN) ? d_deg[i] : 0;
    if (i < NN) d_dinv[i] = rsqrtf((float)v + 1.0f);
    s[tid] = v;
    __syncthreads();
    #pragma unroll
    for (int off = 1; off < 512; off <<= 1) {
        int t = (tid >= off) ? s[tid - off] : 0;
        __syncthreads();
        s[tid] += t;
        __syncthreads();
    }
    if (i < NN) d_rowptr[i + 1] = s[tid];
    if (tid == 511) d_blocksum[blockIdx.x] = s[511];
}
__global__ void scan_add2_kernel() {
    __shared__ int soff;
    int sbk = blockIdx.x >> 1;
    if (threadIdx.x == 0) {
        int o = 0;
        for (int j = 0; j < sbk; j++) o += d_blocksum[j];
        soff = o;
    }
    __syncthreads();
    int i = blockIdx.x * 256 + threadIdx.x;
    if (i == 0) { d_rowptr[0] = 0; d_cursor[0] = 0; }
    if (i < NN) {
        int v = d_rowptr[i + 1] + soff;
        d_rowptr[i + 1] = v;
        if (i + 1 < NN) d_cursor[i + 1] = v;
    }
}

// ---------------- fused fill: csr_fill + xprep + bprep ----------------
__global__ void fused_fill_kernel(const int* __restrict__ ei,
                                  const float* __restrict__ x_seq,
                                  const float* __restrict__ Wih,
                                  const float* __restrict__ Whh) {
    int b = blockIdx.x;
    if (b < 6250) {
        int e = b * 256 + threadIdx.x;
        int s = ei[e];
        int d = ei[EE + e];
        int idx = atomicAdd(&d_cursor[d], 1);
        d_csr[idx] = s;
    } else if (b < 25000) {
        int id = (b - 6250) * 256 + threadIdx.x;
        if (id >= NN * 96) return;
        int n = id / 96, r = id % 96;
        int t = r >> 2, c4 = r & 3;
        float dn = d_dinv[n];
        float4 v = *(const float4*)(x_seq + ((size_t)t * NN + n) * F + c4 * 4);
        __half h[4] = {__float2half_rn(v.x * dn), __float2half_rn(v.y * dn),
                       __float2half_rn(v.z * dn), __float2half_rn(v.w * dn)};
        *(uint2*)(d_xh + (size_t)n * 384 + r * 4) = *(uint2*)h;
    } else {
        int id = (b - 25000) * 256 + threadIdx.x;
        if (id >= 512 * 24) return;
        int cg = id / 24, u = id % 24;
        int nb = cg >> 7, c = cg & 127;
        int wn = c >> 6, g = (c >> 4) & 3, jh = (c >> 3) & 1, s = c & 7;
        int jg = nb * 32 + wn * 16 + jh * 8 + s;
        int G = g * 128 + jg;
        union { __half h[8]; uint4 q; } up;
        #pragma unroll
        for (int e = 0; e < 8; e++) {
            int k = u * 8 + e;
            float v = (k < 64) ? Wih[G * 64 + k] : Whh[G * 128 + (k - 64)];
            up.h[e] = __float2half_rn(v);
        }
        d_Bp[(size_t)cg * 24 + u] = up.q;
    }
}

// ---------------- fused agg1 + mm1 (8-t chunks, dinv folded, MLP8) ----------------
__global__ void __launch_bounds__(256) agg1mm1_kernel(const float* __restrict__ W1,
                                                      const float* __restrict__ b1) {
    __shared__ float W1s[F * H];
    __shared__ float b1s[H];
    __shared__ float ys[8][128];
    int tid = threadIdx.x, w = tid >> 5, lane = tid & 31;
    for (int i = tid; i < F * H; i += 256) W1s[i] = W1[i];
    if (tid < H) b1s[tid] = b1[tid];
    int n = blockIdx.x * 8 + w;
    int q = blockIdx.y;
    float dn = d_dinv[n];
    const uint2* xr = (const uint2*)d_xh;
    uint2 u = xr[(size_t)n * 96 + q * 32 + lane];
    float2 p0 = __half22float2(*(__half2*)&u.x);
    float2 p1 = __half22float2(*(__half2*)&u.y);
    float a0 = p0.x, a1 = p0.y, a2 = p1.x, a3 = p1.y;
    int e = d_rowptr[n], e1 = d_rowptr[n + 1];
    for (; e + 8 <= e1; e += 8) {
        int si[8];
        #pragma unroll
        for (int k = 0; k < 8; k++) si[k] = d_csr[e + k];
        #pragma unroll
        for (int k = 0; k < 8; k++) {
            uint2 v = xr[(size_t)si[k] * 96 + q * 32 + lane];
            float2 q0 = __half22float2(*(__half2*)&v.x);
            float2 q1 = __half22float2(*(__half2*)&v.y);
            a0 += q0.x; a1 += q0.y; a2 += q1.x; a3 += q1.y;
        }
    }
    for (; e < e1; e++) {
        int s = d_csr[e];
        uint2 v = xr[(size_t)s * 96 + q * 32 + lane];
        float2 q0 = __half22float2(*(__half2*)&v.x);
        float2 q1 = __half22float2(*(__half2*)&v.y);
        a0 += q0.x; a1 += q0.y; a2 += q1.x; a3 += q1.y;
    }
    ys[w][lane * 4 + 0] = a0 * dn; ys[w][lane * 4 + 1] = a1 * dn;
    ys[w][lane * 4 + 2] = a2 * dn; ys[w][lane * 4 + 3] = a3 * dn;
    __syncthreads();
    int n2 = tid >> 5, t2 = lane >> 2, jq = lane & 3;
    int ng = blockIdx.x * 8 + n2;
    float dscale = d_dinv[ng];
    float yv[16];
    #pragma unroll
    for (int k = 0; k < 16; k++) yv[k] = ys[n2][t2 * 16 + k];
    float o[16];
    #pragma unroll
    for (int jj = 0; jj < 16; jj++) o[jj] = b1s[jq * 16 + jj];
    #pragma unroll
    for (int k = 0; k < 16; k++)
        #pragma unroll
        for (int jj = 0; jj < 16; jj++)
            o[jj] = fmaf(yv[k], W1s[k * 64 + jq * 16 + jj], o[jj]);
    __half hp[16];
    #pragma unroll
    for (int jj = 0; jj < 16; jj++)
        hp[jj] = __float2half_rn(fmaxf(o[jj], 0.0f) * dscale);
    int t = q * 8 + t2;
    int qq = t >> 2, tt = t & 3;
    __half* dst = d_h1 + (((size_t)qq * NN + ng) * 4 + tt) * 64 + jq * 16;
    *(uint4*)dst = *(uint4*)hp;
    *(uint4*)(dst + 8) = *(uint4*)(hp + 8);
}

// ---------------- fused agg2 + mm2 (4-t chunks, single LDG.128 per edge) ----------------
__global__ void __launch_bounds__(256) agg2mm2_kernel(const float* __restrict__ W2,
                                                      const float* __restrict__ b2) {
    __shared__ float W2s[H * H];
    __shared__ float b2s[H];
    __shared__ float zs[8][4][66];
    int tid = threadIdx.x, w = tid >> 5, lane = tid & 31;
    for (int i = tid; i < H * H; i += 256) W2s[i] = W2[i];
    if (tid < H) b2s[tid] = b2[tid];
    int n = blockIdx.x * 8 + w;
    int q = blockIdx.y;
    float dn = d_dinv[n];
    const uint4* h1q = (const uint4*)d_h1 + (size_t)q * NN * 32;
    float acc[8];
    {
        uint4 sv = h1q[(size_t)n * 32 + lane];
        __half2* h = (__half2*)&sv;
        #pragma unroll
        for (int i = 0; i < 4; i++) {
            float2 p = __half22float2(h[i]);
            acc[2 * i] = p.x; acc[2 * i + 1] = p.y;
        }
    }
    int e = d_rowptr[n], e1 = d_rowptr[n + 1];
    for (; e + 8 <= e1; e += 8) {
        int si[8];
        #pragma unroll
        for (int u2 = 0; u2 < 8; u2++) si[u2] = d_csr[e + u2];
        uint4 v[8];
        #pragma unroll
        for (int u2 = 0; u2 < 8; u2++) v[u2] = h1q[(size_t)si[u2] * 32 + lane];
        #pragma unroll
        for (int u2 = 0; u2 < 8; u2++) acc8(acc, v[u2]);
    }
    for (; e < e1; e++) {
        int s = d_csr[e];
        acc8(acc, h1q[(size_t)s * 32 + lane]);
    }
    {
        int tt = lane >> 3, cb = (lane & 7) * 8;
        #pragma unroll
        for (int i = 0; i < 8; i++) zs[w][tt][cb + i] = acc[i] * dn;
    }
    __syncthreads();
    int n2 = tid >> 5, t2 = (lane >> 3) & 3, j0 = (lane & 7) * 8;
    float o[8];
    #pragma unroll
    for (int jj = 0; jj < 8; jj++) o[jj] = b2s[j0 + jj];
    #pragma unroll 8
    for (int k = 0; k < 64; k++) {
        float zv = zs[n2][t2][k];
        float4 w0 = *(float4*)(W2s + k * 64 + j0);
        float4 w1 = *(float4*)(W2s + k * 64 + j0 + 4);
        o[0] = fmaf(zv, w0.x, o[0]); o[1] = fmaf(zv, w0.y, o[1]);
        o[2] = fmaf(zv, w0.z, o[2]); o[3] = fmaf(zv, w0.w, o[3]);
        o[4] = fmaf(zv, w1.x, o[4]); o[5] = fmaf(zv, w1.y, o[5]);
        o[6] = fmaf(zv, w1.z, o[6]); o[7] = fmaf(zv, w1.w, o[7]);
    }
    __half hp[8];
    #pragma unroll
    for (int jj = 0; jj < 8; jj++)
        hp[jj] = __float2half_rn(fmaxf(o[jj], 0.0f));
    int ng = blockIdx.x * 8 + n2;
    size_t base = ((size_t)(q * 4 + t2) * NPAD + ng) * 64 + j0;
    *(uint4*)(d_h2 + base) = *(uint4*)hp;
}

// ---------------- tile-local LSTM: one CTA = 32 nodes, all 512 gate cols, t-loop ----------------
__global__ void __launch_bounds__(256, 1) lstm_tile(
    const float* __restrict__ bih, const float* __restrict__ bhh,
    const float* __restrict__ Wf1, const float* __restrict__ bf1,
    const float* __restrict__ Wf2, const float* __restrict__ bf2,
    float* __restrict__ out) {
    extern __shared__ char smem[];
    uint32_t sb = smem_u32(smem);
    const int tid = threadIdx.x, lane = tid & 31, wid = tid >> 5;
    const int row0 = blockIdx.x * MTILE;

    // load full B (512 cols x 400B) into smem
    for (int i = tid; i < 512 * 24; i += 256) {
        int col = i / 24, u = i % 24;
        uint4 v = d_Bp[(size_t)col * 24 + u];
        *(uint4*)(smem + BOFF + col * 400 + u * 16) = v;
    }
    // zero A h-section (rows 0..31, bytes 128..384)
    for (int i = tid; i < 512; i += 256) {         // 32 rows x 16 uint4
        int row = i >> 4, u = i & 15;
        *(uint4*)(smem + AOFF + row * 400 + 128 + u * 16) = make_uint4(0, 0, 0, 0);
    }

    // per-thread biases (16 gate values) and c registers
    const int gq = lane >> 2, tq = lane & 3;
    float bsr[16];   // [g][jh][p]
    #pragma unroll
    for (int g = 0; g < 4; g++)
        #pragma unroll
        for (int jh = 0; jh < 2; jh++)
            #pragma unroll
            for (int p = 0; p < 2; p++) {
                int jg = (wid >> 1) * 32 + (wid & 1) * 16 + jh * 8 + 2 * tq + p;
                int idx = g * 128 + jg;
                bsr[g * 4 + jh * 2 + p] = bih[idx] + bhh[idx];
            }
    float creg[16];  // [mi][h][jh][p]
    #pragma unroll
    for (int i = 0; i < 16; i++) creg[i] = 0.0f;

    // stage h2(0): 32 rows x 128B (all 256 threads)
    {
        int row = tid >> 3, u = tid & 7;
        cp16(sb + AOFF + row * 400 + u * 16,
             d_h2 + (size_t)(row0 + row) * 64 + u * 8);
    }
    asm volatile("cp.async.commit_group;" ::: "memory");
    asm volatile("cp.async.wait_group 0;" ::: "memory");
    __syncthreads();

    const int q4 = lane >> 3, r8 = lane & 7;
    const uint32_t aRowOff = (uint32_t)(((q4 & 1) * 8 + r8) * 400 + ((q4 >> 1) * 8) * 2);
    const uint32_t bRowBase = (uint32_t)((wid * 64 + (q4 >> 1) * 8 + r8) * 400 + (q4 & 1) * 16);

    for (int t = 0; t < T_STEPS; t++) {
        float acc[2][8][4];
        #pragma unroll
        for (int mi = 0; mi < 2; mi++)
            #pragma unroll
            for (int nt = 0; nt < 8; nt++)
                #pragma unroll
                for (int r = 0; r < 4; r++) acc[mi][nt][r] = 0.0f;

        uint32_t aB = sb + AOFF + aRowOff;
        uint32_t bB = sb + BOFF + bRowBase;
        #pragma unroll 1
        for (int ks = 0; ks < 12; ks++) {
            uint32_t a[2][4];
            ldsm4(a[0], aB + ks * 32);
            ldsm4(a[1], aB + 16 * 400 + ks * 32);
            uint32_t b[8][2];
            #pragma unroll
            for (int pr = 0; pr < 4; pr++) {
                uint32_t t4[4];
                ldsm4(t4, bB + pr * (16 * 400) + ks * 32);
                b[2 * pr][0] = t4[0]; b[2 * pr][1] = t4[1];
                b[2 * pr + 1][0] = t4[2]; b[2 * pr + 1][1] = t4[3];
            }
            #pragma unroll
            for (int mi = 0; mi < 2; mi++)
                #pragma unroll
                for (int nt = 0; nt < 8; nt++)
                    mma16816(acc[mi][nt], a[mi], b[nt]);
        }
        __syncthreads();

        // prefetch h2(t+1) into A h2-section (all 256 threads, full 128B rows)
        if (t + 1 < T_STEPS) {
            int row = tid >> 3, u = tid & 7;
            cp16(sb + AOFF + row * 400 + u * 16,
                 d_h2 + ((size_t)(t + 1) * NPAD + row0 + row) * 64 + u * 8);
        }
        asm volatile("cp.async.commit_group;" ::: "memory");

        // epilogue: per-thread gates -> c (regs) -> h (smem A h-section)
        #pragma unroll
        for (int mi = 0; mi < 2; mi++) {
            #pragma unroll
            for (int h = 0; h < 2; h++) {
                int rl = mi * 16 + h * 8 + gq;
                #pragma unroll
                for (int jh = 0; jh < 2; jh++) {
                    int jl0 = jh * 8 + 2 * tq;
                    int jg0 = (wid >> 1) * 32 + (wid & 1) * 16 + jl0;
                    __half hout[2];
                    #pragma unroll
                    for (int p = 0; p < 2; p++) {
                        int ci = h * 2 + p;
                        int bi = jh * 2 + p;
                        float gi = acc[mi][0 + jh][ci] + bsr[0 + bi];
                        float gf = acc[mi][2 + jh][ci] + bsr[4 + bi];
                        float gG = acc[mi][4 + jh][ci] + bsr[8 + bi];
                        float go = acc[mi][6 + jh][ci] + bsr[12 + bi];
                        int cidx = mi * 8 + h * 4 + jh * 2 + p;
                        float cn = sigt(gf) * creg[cidx] + sigt(gi) * tanha(gG);
                        creg[cidx] = cn;
                        hout[p] = __float2half_rn(sigt(go) * tanha(cn));
                    }
                    *(uint*)(smem + AOFF + rl * 400 + 128 + jg0 * 2) = *(uint*)hout;
                }
            }
        }
        asm volatile("cp.async.wait_group 0;" ::: "memory");
        __syncthreads();
    }

    // ---- fused FC head: h (fp16, A h-section) -> out ----
    float* Wf1s = (float*)(smem + BOFF);          // reuse B region: 128x32 f32
    float* bf1s = (float*)(smem + BOFF + 16384);
    float* wf2s = (float*)(smem + BOFF + 16384 + 128);
    for (int i = tid; i < 128 * 32; i += 256) Wf1s[i] = Wf1[i];
    if (tid < 32) { bf1s[tid] = bf1[tid]; wf2s[tid] = Wf2[tid]; }
    __syncthreads();
    {
        int node = tid >> 3, e8 = tid & 7;
        const __half* hrow = (const __half*)(smem + AOFF + node * 400 + 128);
        float part = 0.0f;
        #pragma unroll
        for (int jj = 0; jj < 4; jj++) {
            int j = e8 * 4 + jj;
            float z = bf1s[j];
            #pragma unroll 16
            for (int k = 0; k < 128; k++)
                z = fmaf(__half2float(hrow[k]), Wf1s[k * 32 + j], z);
            part = fmaf(fmaxf(z, 0.0f), wf2s[j], part);
        }
        #pragma unroll
        for (int off = 4; off > 0; off >>= 1)
            part += __shfl_down_sync(0xffffffffu, part, off, 8);
        int n = row0 + node;
        if (e8 == 0 && n < NN) out[n] = part + bf2[0];
    }
}

// ---------------- launcher ----------------
extern "C" void kernel_launch(void* const* d_in, const int* in_sizes, int n_in,
                              void* d_out, int out_size) {
    const float* x_seq = (const float*)d_in[0];
    const int*   ei    = (const int*)d_in[1];
    const float* W1    = (const float*)d_in[2];
    const float* b1    = (const float*)d_in[3];
    const float* W2    = (const float*)d_in[4];
    const float* b2    = (const float*)d_in[5];
    const float* Wih   = (const float*)d_in[6];
    const float* Whh   = (const float*)d_in[7];
    const float* bih   = (const float*)d_in[8];
    const float* bhh   = (const float*)d_in[9];
    const float* Wf1   = (const float*)d_in[10];
    const float* bf1   = (const float*)d_in[11];
    const float* Wf2   = (const float*)d_in[12];
    const float* bf2   = (const float*)d_in[13];
    float* out = (float*)d_out;

    cudaFuncSetAttribute(lstm_tile, cudaFuncAttributeMaxDynamicSharedMemorySize,
                         LSTM_SMEM);

    void* degp;
    cudaGetSymbolAddress(&degp, d_deg);
    cudaMemsetAsync(degp, 0, NN * sizeof(int));

    deg_kernel<<<(EE + 255) / 256, 256>>>(ei);
    dinv_scan_kernel<<<SCAN_NB, 512>>>();
    scan_add2_kernel<<<(NN + 255) / 256, 256>>>();
    fused_fill_kernel<<<25048, 256>>>(ei, x_seq, Wih, Whh);
    agg1mm1_kernel<<<dim3(NN / 8, 3), 256>>>(W1, b1);
    agg2mm2_kernel<<<dim3(NN / 8, 6), 256>>>(W2, b2);
    lstm_tile<<<NTILES, 256, LSTM_SMEM>>>(bih, bhh, Wf1, bf1, Wf2, bf2, out);
}

// round 14
// speedup vs baseline: 3.2160x; 1.1752x over previous
#include <cuda_runtime.h>
#include <cuda_bf16.h>
#include <cuda_fp16.h>
#include <math.h>
#include <stdint.h>

#define T_STEPS 24
#define NN 50000
#define NPAD 50048
#define EE 1600000
#define F 16
#define H 64
#define LH 128
#define SCAN_NB 98

#define MTILE 32
#define NTILES (NPAD / MTILE)     // 1564
#define NCTAS 148
#define NPROD (NCTAS * 8)         // 1184 producer warps

// fused kernel smem layout
#define BOFF 0                    // B fp16: 512 x 400 = 204800
#define AOFF 204800               // A: 32 x 400 = 12800
#define W2HOFF 217600             // W2 fp16: 64*64*2 = 8192
#define B2OFF 225792              // b2: 256
#define BIASOFF 226048            // bias: 512 f32 = 2048
#define FUSED_SMEM 228096

// ---------------- helpers ----------------
__device__ __forceinline__ uint32_t smem_u32(const void* p) {
    uint32_t a;
    asm("{ .reg .u64 t; cvta.to.shared.u64 t, %1; cvt.u32.u64 %0, t; }" : "=r"(a) : "l"(p));
    return a;
}
__device__ __forceinline__ void ldsm4(uint32_t* r, uint32_t addr) {
    asm volatile("ldmatrix.sync.aligned.m8n8.x4.shared.b16 {%0,%1,%2,%3}, [%4];"
                 : "=r"(r[0]), "=r"(r[1]), "=r"(r[2]), "=r"(r[3]) : "r"(addr));
}
__device__ __forceinline__ void mma16816(float* c, const uint32_t* a, const uint32_t* b) {
    asm volatile(
        "mma.sync.aligned.m16n8k16.row.col.f32.f16.f16.f32 "
        "{%0,%1,%2,%3}, {%4,%5,%6,%7}, {%8,%9}, {%0,%1,%2,%3};"
        : "+f"(c[0]), "+f"(c[1]), "+f"(c[2]), "+f"(c[3])
        : "r"(a[0]), "r"(a[1]), "r"(a[2]), "r"(a[3]), "r"(b[0]), "r"(b[1]));
}
__device__ __forceinline__ void cp16(uint32_t dst, const void* src) {
    asm volatile("cp.async.cg.shared.global [%0], [%1], 16;" :: "r"(dst), "l"(src));
}
__device__ __forceinline__ float tanha(float x) {
    float r;
    asm("tanh.approx.f32 %0, %1;" : "=f"(r) : "f"(x));
    return r;
}
__device__ __forceinline__ float sigt(float x) {
    return fmaf(tanha(0.5f * x), 0.5f, 0.5f);
}
__device__ __forceinline__ void acc8(float* a, uint4 v) {
    __half2* h = (__half2*)&v;
    #pragma unroll
    for (int i = 0; i < 4; i++) {
        float2 p = __half22float2(h[i]);
        a[2 * i] += p.x; a[2 * i + 1] += p.y;
    }
}
#define BAR_LSTM() asm volatile("bar.sync 1, 256;" ::: "memory")

// ---------------- scratch ----------------
__device__ int   d_deg[NN];
__device__ int   d_rowptr[NN + 1];
__device__ int   d_cursor[NN];
__device__ int   d_csr[EE];
__device__ int   d_blocksum[128];
__device__ float d_dinv[NN];
__device__ unsigned d_done[8];                    // per-chunk producer counters
__device__ __half d_xh[19200000];                 // [n][t*16+c]  (x * dinv[n])
__device__ __half d_h1[76800000];                 // [q][n][4t][64]   (h1 * dinv[n])
__device__ __half d_h2[76873728];                 // [t][NPAD][64] fp16
__device__ __half d_hst[6406144];                 // h state spill [NPAD][128]
__device__ float d_cst[6406144];                  // c state spill [tile][tid][16]
__device__ uint4 d_Bp[512 * 24];                  // fp16 weights, reordered cols

// ---------------- CSR build ----------------
__global__ void deg_kernel(const int* __restrict__ ei) {
    int e = blockIdx.x * 256 + threadIdx.x;
    if (e < EE) atomicAdd(&d_deg[ei[EE + e]], 1);
}
__global__ void dinv_scan_kernel() {
    __shared__ int s[512];
    int tid = threadIdx.x;
    int i = blockIdx.x * 512 + tid;
    int v = (i < NN) ? d_deg[i] : 0;
    if (i < NN) d_dinv[i] = rsqrtf((float)v + 1.0f);
    s[tid] = v;
    __syncthreads();
    #pragma unroll
    for (int off = 1; off < 512; off <<= 1) {
        int t = (tid >= off) ? s[tid - off] : 0;
        __syncthreads();
        s[tid] += t;
        __syncthreads();
    }
    if (i < NN) d_rowptr[i + 1] = s[tid];
    if (tid == 511) d_blocksum[blockIdx.x] = s[511];
}
__global__ void scan_add2_kernel() {
    __shared__ int soff;
    int sbk = blockIdx.x >> 1;
    if (threadIdx.x == 0) {
        int o = 0;
        for (int j = 0; j < sbk; j++) o += d_blocksum[j];
        soff = o;
    }
    __syncthreads();
    int i = blockIdx.x * 256 + threadIdx.x;
    if (i == 0) { d_rowptr[0] = 0; d_cursor[0] = 0; }
    if (i < NN) {
        int v = d_rowptr[i + 1] + soff;
        d_rowptr[i + 1] = v;
        if (i + 1 < NN) d_cursor[i + 1] = v;
    }
}

// ---------------- fused fill: csr_fill + xprep + bprep ----------------
__global__ void fused_fill_kernel(const int* __restrict__ ei,
                                  const float* __restrict__ x_seq,
                                  const float* __restrict__ Wih,
                                  const float* __restrict__ Whh) {
    int b = blockIdx.x;
    if (b < 6250) {
        int e = b * 256 + threadIdx.x;
        int s = ei[e];
        int d = ei[EE + e];
        int idx = atomicAdd(&d_cursor[d], 1);
        d_csr[idx] = s;
    } else if (b < 25000) {
        int id = (b - 6250) * 256 + threadIdx.x;
        if (id >= NN * 96) return;
        int n = id / 96, r = id % 96;
        int t = r >> 2, c4 = r & 3;
        float dn = d_dinv[n];
        float4 v = *(const float4*)(x_seq + ((size_t)t * NN + n) * F + c4 * 4);
        __half h[4] = {__float2half_rn(v.x * dn), __float2half_rn(v.y * dn),
                       __float2half_rn(v.z * dn), __float2half_rn(v.w * dn)};
        *(uint2*)(d_xh + (size_t)n * 384 + r * 4) = *(uint2*)h;
    } else {
        int id = (b - 25000) * 256 + threadIdx.x;
        if (id >= 512 * 24) return;
        int cg = id / 24, u = id % 24;
        int nb = cg >> 7, c = cg & 127;
        int wn = c >> 6, g = (c >> 4) & 3, jh = (c >> 3) & 1, s = c & 7;
        int jg = nb * 32 + wn * 16 + jh * 8 + s;
        int G = g * 128 + jg;
        union { __half h[8]; uint4 q; } up;
        #pragma unroll
        for (int e = 0; e < 8; e++) {
            int k = u * 8 + e;
            float v = (k < 64) ? Wih[G * 64 + k] : Whh[G * 128 + (k - 64)];
            up.h[e] = __float2half_rn(v);
        }
        d_Bp[(size_t)cg * 24 + u] = up.q;
    }
}

// ---------------- fused agg1 + mm1 (8-t chunks, dinv folded, MLP8) ----------------
__global__ void __launch_bounds__(256) agg1mm1_kernel(const float* __restrict__ W1,
                                                      const float* __restrict__ b1) {
    __shared__ float W1s[F * H];
    __shared__ float b1s[H];
    __shared__ float ys[8][128];
    int tid = threadIdx.x, w = tid >> 5, lane = tid & 31;
    for (int i = tid; i < F * H; i += 256) W1s[i] = W1[i];
    if (tid < H) b1s[tid] = b1[tid];
    int n = blockIdx.x * 8 + w;
    int q = blockIdx.y;
    float dn = d_dinv[n];
    const uint2* xr = (const uint2*)d_xh;
    uint2 u = xr[(size_t)n * 96 + q * 32 + lane];
    float2 p0 = __half22float2(*(__half2*)&u.x);
    float2 p1 = __half22float2(*(__half2*)&u.y);
    float a0 = p0.x, a1 = p0.y, a2 = p1.x, a3 = p1.y;
    int e = d_rowptr[n], e1 = d_rowptr[n + 1];
    for (; e + 8 <= e1; e += 8) {
        int si[8];
        #pragma unroll
        for (int k = 0; k < 8; k++) si[k] = d_csr[e + k];
        #pragma unroll
        for (int k = 0; k < 8; k++) {
            uint2 v = xr[(size_t)si[k] * 96 + q * 32 + lane];
            float2 q0 = __half22float2(*(__half2*)&v.x);
            float2 q1 = __half22float2(*(__half2*)&v.y);
            a0 += q0.x; a1 += q0.y; a2 += q1.x; a3 += q1.y;
        }
    }
    for (; e < e1; e++) {
        int s = d_csr[e];
        uint2 v = xr[(size_t)s * 96 + q * 32 + lane];
        float2 q0 = __half22float2(*(__half2*)&v.x);
        float2 q1 = __half22float2(*(__half2*)&v.y);
        a0 += q0.x; a1 += q0.y; a2 += q1.x; a3 += q1.y;
    }
    ys[w][lane * 4 + 0] = a0 * dn; ys[w][lane * 4 + 1] = a1 * dn;
    ys[w][lane * 4 + 2] = a2 * dn; ys[w][lane * 4 + 3] = a3 * dn;
    __syncthreads();
    int n2 = tid >> 5, t2 = lane >> 2, jq = lane & 3;
    int ng = blockIdx.x * 8 + n2;
    float dscale = d_dinv[ng];
    float yv[16];
    #pragma unroll
    for (int k = 0; k < 16; k++) yv[k] = ys[n2][t2 * 16 + k];
    float o[16];
    #pragma unroll
    for (int jj = 0; jj < 16; jj++) o[jj] = b1s[jq * 16 + jj];
    #pragma unroll
    for (int k = 0; k < 16; k++)
        #pragma unroll
        for (int jj = 0; jj < 16; jj++)
            o[jj] = fmaf(yv[k], W1s[k * 64 + jq * 16 + jj], o[jj]);
    __half hp[16];
    #pragma unroll
    for (int jj = 0; jj < 16; jj++)
        hp[jj] = __float2half_rn(fmaxf(o[jj], 0.0f) * dscale);
    int t = q * 8 + t2;
    int qq = t >> 2, tt = t & 3;
    __half* dst = d_h1 + (((size_t)qq * NN + ng) * 4 + tt) * 64 + jq * 16;
    *(uint4*)dst = *(uint4*)hp;
    *(uint4*)(dst + 8) = *(uint4*)(hp + 8);
}

// ---------------- fused producer/consumer: agg2+mm2 producers + tile LSTM + FC ----------------
__global__ void __launch_bounds__(512, 1) fused_lstm(
    const float* __restrict__ bih, const float* __restrict__ bhh,
    const float* __restrict__ W2, const float* __restrict__ b2,
    const float* __restrict__ Wf1, const float* __restrict__ bf1,
    const float* __restrict__ Wf2, const float* __restrict__ bf2,
    float* __restrict__ out) {
    extern __shared__ char smem[];
    uint32_t sb = smem_u32(smem);
    const int tid = threadIdx.x, lane = tid & 31, wid = tid >> 5;
    const int cta = blockIdx.x;

    // one-time smem init (all 512 threads)
    for (int i = tid; i < 512 * 24; i += 512) {
        int col = i / 24, u = i % 24;
        *(uint4*)(smem + BOFF + col * 400 + u * 16) = d_Bp[(size_t)col * 24 + u];
    }
    __half* W2h = (__half*)(smem + W2HOFF);
    for (int i = tid; i < H * H; i += 512) W2h[i] = __float2half_rn(W2[i]);
    float* b2s = (float*)(smem + B2OFF);
    if (tid < H) b2s[tid] = b2[tid];
    float* bs = (float*)(smem + BIASOFF);
    if (tid < 512) bs[tid] = bih[tid] + bhh[tid];
    __syncthreads();

    if (wid >= 8) {
        // ================== PRODUCER: agg2 + mm2 ==================
        int pw = cta * 8 + (wid - 8);          // 0..1183
        int tt_o = lane >> 3, j8 = lane & 7, j0 = j8 * 8;
        float b2r[8];
        #pragma unroll
        for (int jj = 0; jj < 8; jj++) b2r[jj] = b2s[j0 + jj];
        for (int q = 0; q < 6; q++) {
            const uint4* h1q = (const uint4*)d_h1 + (size_t)q * NN * 32;
            for (int n = pw; n < NN; n += NPROD) {
                float dn = d_dinv[n];
                float acc[8];
                {
                    uint4 sv = h1q[(size_t)n * 32 + lane];
                    __half2* h = (__half2*)&sv;
                    #pragma unroll
                    for (int i = 0; i < 4; i++) {
                        float2 p = __half22float2(h[i]);
                        acc[2 * i] = p.x; acc[2 * i + 1] = p.y;
                    }
                }
                int e = d_rowptr[n], e1 = d_rowptr[n + 1];
                for (; e + 8 <= e1; e += 8) {
                    int si[8];
                    #pragma unroll
                    for (int u2 = 0; u2 < 8; u2++) si[u2] = d_csr[e + u2];
                    uint4 v[8];
                    #pragma unroll
                    for (int u2 = 0; u2 < 8; u2++) v[u2] = h1q[(size_t)si[u2] * 32 + lane];
                    #pragma unroll
                    for (int u2 = 0; u2 < 8; u2++) acc8(acc, v[u2]);
                }
                for (; e < e1; e++)
                    acc8(acc, h1q[(size_t)d_csr[e] * 32 + lane]);
                #pragma unroll
                for (int i = 0; i < 8; i++) acc[i] *= dn;
                // mm2: z via shuffle, W2 fp16 from smem
                float o[8];
                #pragma unroll
                for (int jj = 0; jj < 8; jj++) o[jj] = b2r[jj];
                #pragma unroll 8
                for (int k = 0; k < 64; k++) {
                    float zk = __shfl_sync(0xffffffffu, acc[k & 7],
                                           (lane & 24) + (k >> 3));
                    uint4 wv = *(uint4*)(W2h + k * 64 + j0);
                    __half2* wh = (__half2*)&wv;
                    #pragma unroll
                    for (int i = 0; i < 4; i++) {
                        float2 wp = __half22float2(wh[i]);
                        o[2 * i] = fmaf(zk, wp.x, o[2 * i]);
                        o[2 * i + 1] = fmaf(zk, wp.y, o[2 * i + 1]);
                    }
                }
                __half hp[8];
                #pragma unroll
                for (int jj = 0; jj < 8; jj++)
                    hp[jj] = __float2half_rn(fmaxf(o[jj], 0.0f));
                *(uint4*)(d_h2 + ((size_t)(q * 4 + tt_o) * NPAD + n) * 64 + j0) = *(uint4*)hp;
            }
            __threadfence();
            __syncwarp();
            if (lane == 0) atomicAdd(&d_done[q], 1u);
        }
        return;
    }

    // ================== CONSUMER: tile LSTM, chunk-major ==================
    const int ntile = (cta < NTILES - NCTAS * 10) ? 11 : 10;   // 1564 = 84*11 + 64*10
    const int gq = lane >> 2, tq = lane & 3;
    const int q4 = lane >> 3, r8 = lane & 7;
    const uint32_t aRowOff = (uint32_t)(((q4 & 1) * 8 + r8) * 400 + ((q4 >> 1) * 8) * 2);
    const uint32_t bRowBase = (uint32_t)((wid * 64 + (q4 >> 1) * 8 + r8) * 400 + (q4 & 1) * 16);

    for (int q = 0; q < 6; q++) {
        // wait for chunk q
        if (tid == 0) {
            unsigned v;
            do {
                asm volatile("ld.acquire.gpu.global.u32 %0, [%1];"
                             : "=r"(v) : "l"(&d_done[q]) : "memory");
                if (v < NPROD) asm volatile("nanosleep.u32 128;");
            } while (v < NPROD);
        }
        BAR_LSTM();

        for (int k = 0; k < ntile; k++) {
            int tile = cta + k * NCTAS;
            int row0 = tile * MTILE;
            // stage h2(q*4): 32 rows x 128B
            {
                int row = tid >> 3, u = tid & 7;
                cp16(sb + AOFF + row * 400 + u * 16,
                     d_h2 + ((size_t)(q * 4) * NPAD + row0 + row) * 64 + u * 8);
            }
            asm volatile("cp.async.commit_group;" ::: "memory");
            // state: c regs + h smem section (32 rows x 256B = 512 uint4)
            float creg[16];
            if (q == 0) {
                #pragma unroll
                for (int i = 0; i < 16; i++) creg[i] = 0.0f;
                for (int i = tid; i < 512; i += 256) {
                    int row = i >> 4, u = i & 15;
                    *(uint4*)(smem + AOFF + row * 400 + 128 + u * 16) =
                        make_uint4(0, 0, 0, 0);
                }
            } else {
                const float4* cp4 = (const float4*)(d_cst + ((size_t)tile * 256 + tid) * 16);
                #pragma unroll
                for (int i = 0; i < 4; i++) {
                    float4 v = cp4[i];
                    creg[4 * i] = v.x; creg[4 * i + 1] = v.y;
                    creg[4 * i + 2] = v.z; creg[4 * i + 3] = v.w;
                }
                for (int i = tid; i < 512; i += 256) {
                    int row = i >> 4, u = i & 15;
                    *(uint4*)(smem + AOFF + row * 400 + 128 + u * 16) =
                        *(const uint4*)(d_hst + (size_t)(row0 + row) * 128 + u * 8);
                }
            }
            asm volatile("cp.async.wait_group 0;" ::: "memory");
            BAR_LSTM();

            for (int t = q * 4; t < q * 4 + 4; t++) {
                float acc[2][8][4];
                #pragma unroll
                for (int mi = 0; mi < 2; mi++)
                    #pragma unroll
                    for (int nt = 0; nt < 8; nt++)
                        #pragma unroll
                        for (int r = 0; r < 4; r++) acc[mi][nt][r] = 0.0f;

                uint32_t aB = sb + AOFF + aRowOff;
                uint32_t bB = sb + BOFF + bRowBase;
                #pragma unroll 1
                for (int ks = 0; ks < 12; ks++) {
                    uint32_t a[2][4];
                    ldsm4(a[0], aB + ks * 32);
                    ldsm4(a[1], aB + 16 * 400 + ks * 32);
                    #pragma unroll
                    for (int pr = 0; pr < 4; pr++) {
                        uint32_t t4[4];
                        ldsm4(t4, bB + pr * (16 * 400) + ks * 32);
                        uint32_t b0[2] = {t4[0], t4[1]};
                        uint32_t b1v[2] = {t4[2], t4[3]};
                        #pragma unroll
                        for (int mi = 0; mi < 2; mi++) {
                            mma16816(acc[mi][2 * pr], a[mi], b0);
                            mma16816(acc[mi][2 * pr + 1], a[mi], b1v);
                        }
                    }
                }
                BAR_LSTM();

                // prefetch h2(t+1) within chunk
                if (t + 1 < q * 4 + 4) {
                    int row = tid >> 3, u = tid & 7;
                    cp16(sb + AOFF + row * 400 + u * 16,
                         d_h2 + ((size_t)(t + 1) * NPAD + row0 + row) * 64 + u * 8);
                }
                asm volatile("cp.async.commit_group;" ::: "memory");

                // epilogue
                #pragma unroll
                for (int mi = 0; mi < 2; mi++) {
                    #pragma unroll
                    for (int h = 0; h < 2; h++) {
                        int rl = mi * 16 + h * 8 + gq;
                        #pragma unroll
                        for (int jh = 0; jh < 2; jh++) {
                            int jl0 = jh * 8 + 2 * tq;
                            int jg0 = (wid >> 1) * 32 + (wid & 1) * 16 + jl0;
                            __half hout[2];
                            #pragma unroll
                            for (int p = 0; p < 2; p++) {
                                int jg = jg0 + p;
                                int ci = h * 2 + p;
                                float gi = acc[mi][0 + jh][ci] + bs[jg];
                                float gf = acc[mi][2 + jh][ci] + bs[128 + jg];
                                float gG = acc[mi][4 + jh][ci] + bs[256 + jg];
                                float go = acc[mi][6 + jh][ci] + bs[384 + jg];
                                int cidx = mi * 8 + h * 4 + jh * 2 + p;
                                float cn = sigt(gf) * creg[cidx] + sigt(gi) * tanha(gG);
                                creg[cidx] = cn;
                                hout[p] = __float2half_rn(sigt(go) * tanha(cn));
                            }
                            *(uint*)(smem + AOFF + rl * 400 + 128 + jg0 * 2) = *(uint*)hout;
                        }
                    }
                }
                asm volatile("cp.async.wait_group 0;" ::: "memory");
                BAR_LSTM();
            }

            if (q < 5) {
                // spill state: c regs + full h section (512 uint4)
                float4* cp4 = (float4*)(d_cst + ((size_t)tile * 256 + tid) * 16);
                #pragma unroll
                for (int i = 0; i < 4; i++)
                    cp4[i] = make_float4(creg[4 * i], creg[4 * i + 1],
                                         creg[4 * i + 2], creg[4 * i + 3]);
                for (int i = tid; i < 512; i += 256) {
                    int row = i >> 4, u = i & 15;
                    *(uint4*)(d_hst + (size_t)(row0 + row) * 128 + u * 8) =
                        *(const uint4*)(smem + AOFF + row * 400 + 128 + u * 16);
                }
            } else {
                // fused FC head from smem h
                int node = tid >> 3, e8 = tid & 7;
                const __half* hrow = (const __half*)(smem + AOFF + node * 400 + 128);
                float part = 0.0f;
                #pragma unroll
                for (int jj = 0; jj < 4; jj++) {
                    int j = e8 * 4 + jj;
                    float z = __ldg(bf1 + j);
                    #pragma unroll 8
                    for (int kk = 0; kk < 128; kk++)
                        z = fmaf(__half2float(hrow[kk]), __ldg(Wf1 + kk * 32 + j), z);
                    part = fmaf(fmaxf(z, 0.0f), __ldg(Wf2 + j), part);
                }
                #pragma unroll
                for (int off = 4; off > 0; off >>= 1)
                    part += __shfl_down_sync(0xffffffffu, part, off, 8);
                int n = row0 + node;
                if (e8 == 0 && n < NN) out[n] = part + __ldg(bf2);
                BAR_LSTM();
            }
        }
    }
}

// ---------------- launcher ----------------
extern "C" void kernel_launch(void* const* d_in, const int* in_sizes, int n_in,
                              void* d_out, int out_size) {
    const float* x_seq = (const float*)d_in[0];
    const int*   ei    = (const int*)d_in[1];
    const float* W1    = (const float*)d_in[2];
    const float* b1    = (const float*)d_in[3];
    const float* W2    = (const float*)d_in[4];
    const float* b2    = (const float*)d_in[5];
    const float* Wih   = (const float*)d_in[6];
    const float* Whh   = (const float*)d_in[7];
    const float* bih   = (const float*)d_in[8];
    const float* bhh   = (const float*)d_in[9];
    const float* Wf1   = (const float*)d_in[10];
    const float* bf1   = (const float*)d_in[11];
    const float* Wf2   = (const float*)d_in[12];
    const float* bf2   = (const float*)d_in[13];
    float* out = (float*)d_out;

    cudaFuncSetAttribute(fused_lstm, cudaFuncAttributeMaxDynamicSharedMemorySize,
                         FUSED_SMEM);

    void *degp, *donep;
    cudaGetSymbolAddress(&degp, d_deg);
    cudaGetSymbolAddress(&donep, d_done);
    cudaMemsetAsync(degp, 0, NN * sizeof(int));
    cudaMemsetAsync(donep, 0, 8 * sizeof(unsigned));

    deg_kernel<<<(EE + 255) / 256, 256>>>(ei);
    dinv_scan_kernel<<<SCAN_NB, 512>>>();
    scan_add2_kernel<<<(NN + 255) / 256, 256>>>();
    fused_fill_kernel<<<25048, 256>>>(ei, x_seq, Wih, Whh);
    agg1mm1_kernel<<<dim3(NN / 8, 3), 256>>>(W1, b1);
    fused_lstm<<<NCTAS, 512, FUSED_SMEM>>>(bih, bhh, W2, b2, Wf1, bf1, Wf2, bf2, out);
}